// round 3
// baseline (speedup 1.0000x reference)
#include <cuda_runtime.h>
#include <math.h>

#define BSZ   4096
#define NND   32
#define ZDIM  128
#define HID   256
#define INF   64
#define TB    32
#define NTHR  512
#define NCTA  (BSZ / TB)

#define ZST   136   // mult of 8 -> 32B-aligned k8 rows
#define GST   68    // mult of 4 -> float4 stores
#define SST   129   // padded stride for output stage

typedef unsigned long long ull;

// transposed weights (device scratch; rebuilt every launch, deterministic)
__device__ __align__(16) float g_W1T[HID * HID];
__device__ __align__(16) float g_W2T[HID * HID];
__device__ __align__(16) float g_W0T[HID * INF];

__global__ void transpose_k(const float* __restrict__ W0,
                            const float* __restrict__ W1,
                            const float* __restrict__ W2)
{
    int i = blockIdx.x * blockDim.x + threadIdx.x;
    if (i < HID * HID) {
        int r = i >> 8;      // source row (k)
        int c = i & 255;     // source col (j)
        g_W1T[c * HID + r] = W1[i];
        g_W2T[c * HID + r] = W2[i];
        if (r < INF) g_W0T[c * INF + r] = W0[i];
    }
}

// ---- packed f32x2 helpers (sm_103a) ----
__device__ __forceinline__ ull ff2(ull a, ull b, ull c) {
    ull d; asm("fma.rn.f32x2 %0, %1, %2, %3;" : "=l"(d) : "l"(a), "l"(b), "l"(c)); return d;
}
__device__ __forceinline__ float2 upk(ull a) {
    float2 r; asm("mov.b64 {%0, %1}, %2;" : "=f"(r.x), "=f"(r.y) : "l"(a)); return r;
}
__device__ __forceinline__ float hsum(ull a) { float2 u = upk(a); return u.x + u.y; }

// acc[i][j] accumulates (even-k, odd-k) partial dot products:
//   out[s0+i][f4+j] = hsum(acc[i][j])
// in:  activations, row (s0+i), k contiguous (smem, broadcast loads)
// W:   rows contiguous along summation axis k, row stride wstride
__device__ __forceinline__ void mmv2(ull acc[4][4],
                                     const float* in, int istride,
                                     const float* __restrict__ W, int K, int wstride,
                                     int f4, int s0)
{
    for (int k8 = 0; k8 < K; k8 += 8) {
        ulonglong2 h[4][2];
        #pragma unroll
        for (int i = 0; i < 4; i++) {
            const float* hp = in + (s0 + i) * istride + k8;
            h[i][0] = *(const ulonglong2*)(hp);
            h[i][1] = *(const ulonglong2*)(hp + 4);
        }
        #pragma unroll
        for (int j = 0; j < 4; j++) {
            const float* wp = W + (f4 + j) * wstride + k8;
            ulonglong2 w0 = *(const ulonglong2*)(wp);
            ulonglong2 w1 = *(const ulonglong2*)(wp + 4);
            #pragma unroll
            for (int i = 0; i < 4; i++) {
                acc[i][j] = ff2(h[i][0].x, w0.x, acc[i][j]);
                acc[i][j] = ff2(h[i][0].y, w0.y, acc[i][j]);
                acc[i][j] = ff2(h[i][1].x, w1.x, acc[i][j]);
                acc[i][j] = ff2(h[i][1].y, w1.y, acc[i][j]);
            }
        }
    }
}

// fast softplus + sigmoid: sp = max(a,0)+log(1+e), sig = sigmoid(a), e = exp(-|a|)
__device__ __forceinline__ void act2(float a, float& sp, float& sg) {
    float e = __expf(-fabsf(a));
    float d = 1.0f + e;
    sp = fmaxf(a, 0.f) + __logf(d);
    sg = (a >= 0.f) ? __fdividef(1.0f, d) : __fdividef(e, d);
}

__global__ __launch_bounds__(NTHR, 1)
void chnn_kernel(const float* __restrict__ z,
                 const float* __restrict__ m_params,
                 const float* __restrict__ W0, const float* __restrict__ b0,
                 const float* __restrict__ W1, const float* __restrict__ b1,
                 const float* __restrict__ W2, const float* __restrict__ b2,
                 const float* __restrict__ W3,
                 float* __restrict__ out)
{
    extern __shared__ float sm[];
    float* zbuf = sm;                       // TB*ZST  = 4352
    float* bufA = zbuf + TB * ZST;          // TB*HID  = 8192
    float* bufB = bufA + TB * HID;          // 8192
    float* sig0 = bufB + TB * HID;          // 8192
    float* sig1 = sig0 + TB * HID;          // 8192
    float* gbuf = sig1 + TB * HID;          // TB*GST  = 2176
    float* invm = gbuf + TB * GST;          // 32

    const int tid  = threadIdx.x;
    const int blk  = blockIdx.x;
    const int f4   = (tid & 63) * 4;        // 4 consecutive features per thread
    const int s0   = (tid >> 6) * 4;        // 4 samples per thread

    // cooperative load of z tile (padded rows)
    const float* zg = z + (size_t)blk * TB * ZDIM;
    for (int i = tid; i < TB * ZDIM; i += NTHR)
        zbuf[(i >> 7) * ZST + (i & 127)] = zg[i];
    if (tid < NND) invm[tid] = __expf(-m_params[tid]);
    __syncthreads();

    ull acc[4][4];

    // ============ L0: a0 = r @ W0 + b0 ; h0 -> bufA, sig0 ============
    {
        #pragma unroll
        for (int i = 0; i < 4; i++)
            #pragma unroll
            for (int j = 0; j < 4; j++) acc[i][j] = 0ull;
        mmv2(acc, zbuf, ZST, g_W0T, INF, INF, f4, s0);
        const float4 bv = *(const float4*)(b0 + f4);
        const float bb[4] = {bv.x, bv.y, bv.z, bv.w};
        #pragma unroll
        for (int i = 0; i < 4; i++) {
            float hb[4], sb[4];
            #pragma unroll
            for (int j = 0; j < 4; j++)
                act2(hsum(acc[i][j]) + bb[j], hb[j], sb[j]);
            int o = (s0 + i) * HID + f4;
            *(float4*)(bufA + o) = make_float4(hb[0], hb[1], hb[2], hb[3]);
            *(float4*)(sig0 + o) = make_float4(sb[0], sb[1], sb[2], sb[3]);
        }
    }
    __syncthreads();

    // ============ L1: h1 -> bufB, sig1 ============
    {
        #pragma unroll
        for (int i = 0; i < 4; i++)
            #pragma unroll
            for (int j = 0; j < 4; j++) acc[i][j] = 0ull;
        mmv2(acc, bufA, HID, g_W1T, HID, HID, f4, s0);
        const float4 bv = *(const float4*)(b1 + f4);
        const float bb[4] = {bv.x, bv.y, bv.z, bv.w};
        #pragma unroll
        for (int i = 0; i < 4; i++) {
            float hb[4], sb[4];
            #pragma unroll
            for (int j = 0; j < 4; j++)
                act2(hsum(acc[i][j]) + bb[j], hb[j], sb[j]);
            int o = (s0 + i) * HID + f4;
            *(float4*)(bufB + o) = make_float4(hb[0], hb[1], hb[2], hb[3]);
            *(float4*)(sig1 + o) = make_float4(sb[0], sb[1], sb[2], sb[3]);
        }
    }
    __syncthreads();

    // ============ L2 fused with da2 = W3[f]*sigmoid(a2) -> bufA ============
    {
        #pragma unroll
        for (int i = 0; i < 4; i++)
            #pragma unroll
            for (int j = 0; j < 4; j++) acc[i][j] = 0ull;
        mmv2(acc, bufB, HID, g_W2T, HID, HID, f4, s0);
        const float4 bv = *(const float4*)(b2 + f4);
        const float bb[4] = {bv.x, bv.y, bv.z, bv.w};
        const float4 w3v = *(const float4*)(W3 + f4);
        const float wv[4] = {w3v.x, w3v.y, w3v.z, w3v.w};
        #pragma unroll
        for (int i = 0; i < 4; i++) {
            float db[4];
            #pragma unroll
            for (int j = 0; j < 4; j++) {
                float a = hsum(acc[i][j]) + bb[j];
                float e = __expf(-fabsf(a));
                float d = 1.0f + e;
                float sg = (a >= 0.f) ? __fdividef(1.0f, d) : __fdividef(e, d);
                db[j] = wv[j] * sg;
            }
            *(float4*)(bufA + (s0 + i) * HID + f4) = make_float4(db[0], db[1], db[2], db[3]);
        }
    }
    __syncthreads();

    // ============ B1: dh1 = da2 @ W2^T ; da1 = dh1*sig1 -> bufB ============
    // W2 rows are contiguous along summation axis j -> use W2 directly
    {
        #pragma unroll
        for (int i = 0; i < 4; i++)
            #pragma unroll
            for (int j = 0; j < 4; j++) acc[i][j] = 0ull;
        mmv2(acc, bufA, HID, W2, HID, HID, f4, s0);
        #pragma unroll
        for (int i = 0; i < 4; i++) {
            int o = (s0 + i) * HID + f4;
            float4 sg4 = *(const float4*)(sig1 + o);
            *(float4*)(bufB + o) = make_float4(hsum(acc[i][0]) * sg4.x,
                                               hsum(acc[i][1]) * sg4.y,
                                               hsum(acc[i][2]) * sg4.z,
                                               hsum(acc[i][3]) * sg4.w);
        }
    }
    __syncthreads();

    // ============ B2: dh0 = da1 @ W1^T ; da0 = dh0*sig0 -> bufA ============
    {
        #pragma unroll
        for (int i = 0; i < 4; i++)
            #pragma unroll
            for (int j = 0; j < 4; j++) acc[i][j] = 0ull;
        mmv2(acc, bufB, HID, W1, HID, HID, f4, s0);
        #pragma unroll
        for (int i = 0; i < 4; i++) {
            int o = (s0 + i) * HID + f4;
            float4 sg4 = *(const float4*)(sig0 + o);
            *(float4*)(bufA + o) = make_float4(hsum(acc[i][0]) * sg4.x,
                                               hsum(acc[i][1]) * sg4.y,
                                               hsum(acc[i][2]) * sg4.z,
                                               hsum(acc[i][3]) * sg4.w);
        }
    }
    __syncthreads();

    // ============ B3: g = dV/dr = da0 @ W0^T (256 -> 64) -> gbuf ============
    // g[m] = sum_j da0[j] * W0[m][j] -> W0 rows direct (contiguous in j)
    {
        const int fm = (tid & 15) * 4;
        const int s  = tid >> 4;
        ull a4[4] = {0ull, 0ull, 0ull, 0ull};
        for (int k8 = 0; k8 < HID; k8 += 8) {
            const float* hp = bufA + s * HID + k8;
            ulonglong2 h0 = *(const ulonglong2*)(hp);
            ulonglong2 h1 = *(const ulonglong2*)(hp + 4);
            #pragma unroll
            for (int j = 0; j < 4; j++) {
                const float* wp = W0 + (fm + j) * HID + k8;
                ulonglong2 w0 = *(const ulonglong2*)(wp);
                ulonglong2 w1 = *(const ulonglong2*)(wp + 4);
                a4[j] = ff2(h0.x, w0.x, a4[j]);
                a4[j] = ff2(h0.y, w0.y, a4[j]);
                a4[j] = ff2(h1.x, w1.x, a4[j]);
                a4[j] = ff2(h1.y, w1.y, a4[j]);
            }
        }
        *(float4*)(gbuf + s * GST + fm) =
            make_float4(hsum(a4[0]), hsum(a4[1]), hsum(a4[2]), hsum(a4[3]));
    }
    __syncthreads();

    // ============ constraint solve: 1 thread / sample ============
    // A = [[0,G],[-G,S]] with G = E^T M^-1 E tridiagonal SPD (32x32),
    // S tridiagonal antisymmetric. Two Thomas solves.
    float* scr = sig0;  // sig0+sig1 (16384 floats) free now
    float* Ex  = scr + 0  * NND * TB;
    float* Ey  = scr + 1  * NND * TB;
    float* Edx = scr + 2  * NND * TB;
    float* Edy = scr + 3  * NND * TB;
    float* Vx  = scr + 4  * NND * TB;
    float* Vy  = scr + 5  * NND * TB;
    float* Dd  = scr + 6  * NND * TB;
    float* Du  = scr + 7  * NND * TB;
    float* Dl  = scr + 8  * NND * TB;
    float* So  = scr + 9  * NND * TB;
    float* R0  = scr + 10 * NND * TB;   // b0 -> x1
    float* R1  = scr + 11 * NND * TB;   // b1 -> y -> x0

    if (tid < TB) {
        const int s = tid;
        const float* zr = zbuf + s * ZST;

        // build E_c, Edot_c, v  (E_0 = 2 r_0; E_c = 2(r_{c-1}-r_c))
        {
            float prx = zr[0], pry = zr[1];
            float im  = invm[0];
            float pvx = zr[64] * im, pvy = zr[65] * im;
            Ex[s]  = 2.f * prx;  Ey[s]  = 2.f * pry;
            Edx[s] = 2.f * pvx;  Edy[s] = 2.f * pvy;
            Vx[s] = pvx; Vy[s] = pvy;
            for (int c = 1; c < NND; c++) {
                float rx = zr[2*c], ry = zr[2*c+1];
                float imc = invm[c];
                float vx = zr[64 + 2*c] * imc, vy = zr[65 + 2*c] * imc;
                Ex[c*TB+s]  = 2.f*(prx - rx);  Ey[c*TB+s]  = 2.f*(pry - ry);
                Edx[c*TB+s] = 2.f*(pvx - vx);  Edy[c*TB+s] = 2.f*(pvy - vy);
                Vx[c*TB+s] = vx; Vy[c*TB+s] = vy;
                prx = rx; pry = ry; pvx = vx; pvy = vy;
            }
        }
        // tridiagonal G (Dd diag, Du upper), S offdiag (So), rhs b0 (R0), b1 (R1)
        {
            float e0x = Ex[s],  e0y = Ey[s];
            float d0x = Edx[s], d0y = Edy[s];
            float v0x = Vx[s],  v0y = Vy[s];
            float im0 = invm[0];
            float e1x = Ex[TB+s],  e1y = Ey[TB+s];
            float d1x = Edx[TB+s], d1y = Edy[TB+s];
            Dd[s] = im0 * (e0x*e0x + e0y*e0y);
            Du[s] = im0 * (e0x*e1x + e0y*e1y);
            So[s] = im0 * (d0x*e1x + d0y*e1y - d1x*e0x - d1y*e0y);
            R0[s] = e0x*v0x + e0y*v0y;
            float g0x = gbuf[s*GST + 0], g0y = gbuf[s*GST + 1];
            R1[s] = d0x*v0x + d0y*v0y - im0*(e0x*g0x + e0y*g0y);
            for (int c = 1; c < NND; c++) {
                float ecx = Ex[c*TB+s],  ecy = Ey[c*TB+s];
                float dcx = Edx[c*TB+s], dcy = Edy[c*TB+s];
                float imc = invm[c], imp = invm[c-1];
                Dd[c*TB+s] = (imp + imc) * (ecx*ecx + ecy*ecy);
                R0[c*TB+s] = 0.5f * (ecx*dcx + ecy*dcy);
                float gpx = gbuf[s*GST + 2*(c-1)], gpy = gbuf[s*GST + 2*(c-1)+1];
                float gcx = gbuf[s*GST + 2*c],     gcy = gbuf[s*GST + 2*c+1];
                R1[c*TB+s] = 0.5f*(dcx*dcx + dcy*dcy)
                           - (ecx*(imp*gpx - imc*gcx) + ecy*(imp*gpy - imc*gcy));
                if (c < NND - 1) {
                    float enx = Ex[(c+1)*TB+s],  eny = Ey[(c+1)*TB+s];
                    float dnx = Edx[(c+1)*TB+s], dny = Edy[(c+1)*TB+s];
                    Du[c*TB+s] = -imc * (ecx*enx + ecy*eny);
                    So[c*TB+s] =  imc * (dnx*ecx + dny*ecy - dcx*enx - dcy*eny);
                }
            }
        }
        // Thomas factorization of G
        for (int c = 1; c < NND; c++) {
            float l = Du[(c-1)*TB+s] / Dd[(c-1)*TB+s];
            Dl[c*TB+s] = l;
            Dd[c*TB+s] = Dd[c*TB+s] - l * Du[(c-1)*TB+s];
        }
        // solve G x1 = b0 (in place in R0)
        for (int c = 1; c < NND; c++)
            R0[c*TB+s] -= Dl[c*TB+s] * R0[(c-1)*TB+s];
        R0[(NND-1)*TB+s] /= Dd[(NND-1)*TB+s];
        for (int c = NND - 2; c >= 0; c--)
            R0[c*TB+s] = (R0[c*TB+s] - Du[c*TB+s] * R0[(c+1)*TB+s]) / Dd[c*TB+s];
        // y = S x1 - b1 (into R1)
        R1[s] = So[s] * R0[TB+s] - R1[s];
        for (int c = 1; c < NND - 1; c++)
            R1[c*TB+s] = So[c*TB+s]*R0[(c+1)*TB+s] - So[(c-1)*TB+s]*R0[(c-1)*TB+s] - R1[c*TB+s];
        R1[(NND-1)*TB+s] = -So[(NND-2)*TB+s]*R0[(NND-2)*TB+s] - R1[(NND-1)*TB+s];
        // solve G x0 = y (in place in R1)
        for (int c = 1; c < NND; c++)
            R1[c*TB+s] -= Dl[c*TB+s] * R1[(c-1)*TB+s];
        R1[(NND-1)*TB+s] /= Dd[(NND-1)*TB+s];
        for (int c = NND - 2; c >= 0; c--)
            R1[c*TB+s] = (R1[c*TB+s] - Du[c*TB+s]*R1[(c+1)*TB+s]) / Dd[c*TB+s];

        // output: out_r = v - M^-1 (E x1);  out_p = -g + (E x0) + (Edot x1)
        float* st = bufB + s * SST;
        for (int i = 0; i < NND; i++) {
            float eix = Ex[i*TB+s],  eiy = Ey[i*TB+s];
            float dix = Edx[i*TB+s], diy = Edy[i*TB+s];
            float x1i = R0[i*TB+s],  x0i = R1[i*TB+s];
            float p1x, p1y, p0x, p0y, pdx, pdy;
            if (i == 0) {
                float enx = Ex[TB+s],  eny = Ey[TB+s];
                float dnx = Edx[TB+s], dny = Edy[TB+s];
                float x1n = R0[TB+s],  x0n = R1[TB+s];
                p1x = eix*x1i + enx*x1n;  p1y = eiy*x1i + eny*x1n;
                p0x = eix*x0i + enx*x0n;  p0y = eiy*x0i + eny*x0n;
                pdx = dix*x1i + dnx*x1n;  pdy = diy*x1i + dny*x1n;
            } else if (i < NND - 1) {
                float enx = Ex[(i+1)*TB+s],  eny = Ey[(i+1)*TB+s];
                float dnx = Edx[(i+1)*TB+s], dny = Edy[(i+1)*TB+s];
                float x1n = R0[(i+1)*TB+s],  x0n = R1[(i+1)*TB+s];
                p1x = -eix*x1i + enx*x1n;  p1y = -eiy*x1i + eny*x1n;
                p0x = -eix*x0i + enx*x0n;  p0y = -eiy*x0i + eny*x0n;
                pdx = -dix*x1i + dnx*x1n;  pdy = -diy*x1i + dny*x1n;
            } else {
                p1x = -eix*x1i; p1y = -eiy*x1i;
                p0x = -eix*x0i; p0y = -eiy*x0i;
                pdx = -dix*x1i; pdy = -diy*x1i;
            }
            float imi = invm[i];
            st[2*i]     = Vx[i*TB+s] - imi * p1x;
            st[2*i + 1] = Vy[i*TB+s] - imi * p1y;
            float gx = gbuf[s*GST + 2*i], gy = gbuf[s*GST + 2*i + 1];
            st[64 + 2*i]     = -gx + p0x + pdx;
            st[64 + 2*i + 1] = -gy + p0y + pdy;
        }
    }
    __syncthreads();

    // coalesced store of staged output
    float* outg = out + (size_t)blk * TB * ZDIM;
    for (int i = tid; i < TB * ZDIM; i += NTHR)
        outg[i] = bufB[(i >> 7) * SST + (i & 127)];
}

extern "C" void kernel_launch(void* const* d_in, const int* in_sizes, int n_in,
                              void* d_out, int out_size)
{
    (void)in_sizes; (void)n_in; (void)out_size;
    const float* z  = (const float*)d_in[1];
    const float* mp = (const float*)d_in[2];
    const float* W0 = (const float*)d_in[3];
    const float* b0 = (const float*)d_in[4];
    const float* W1 = (const float*)d_in[5];
    const float* b1 = (const float*)d_in[6];
    const float* W2 = (const float*)d_in[7];
    const float* b2 = (const float*)d_in[8];
    const float* W3 = (const float*)d_in[9];
    float* out = (float*)d_out;

    transpose_k<<<(HID * HID + 255) / 256, 256>>>(W0, W1, W2);

    size_t smem = (size_t)(TB * ZST + 4 * TB * HID + TB * GST + 32) * sizeof(float);
    cudaFuncSetAttribute(chnn_kernel, cudaFuncAttributeMaxDynamicSharedMemorySize, (int)smem);
    chnn_kernel<<<NCTA, NTHR, smem>>>(z, mp, W0, b0, W1, b1, W2, b2, W3, out);
}

// round 4
// speedup vs baseline: 3.0316x; 3.0316x over previous
#include <cuda_runtime.h>
#include <math.h>

#define BSZ   4096
#define NND   32
#define ZDIM  128
#define HID   256
#define INF   64
#define TB    32
#define NTHR  512
#define NCTA  (BSZ / TB)

#define TS    36    // sample stride of feature-major tiles (36*4B = 9*16B, float4-aligned rows)
#define GST   68

typedef unsigned long long ull;

// transposed weights (device scratch; rebuilt every launch, deterministic)
__device__ __align__(16) float g_W1T[HID * HID];
__device__ __align__(16) float g_W2T[HID * HID];
__device__ __align__(16) float g_W0T[HID * INF];

__global__ void transpose_k(const float* __restrict__ W0,
                            const float* __restrict__ W1,
                            const float* __restrict__ W2)
{
    int i = blockIdx.x * blockDim.x + threadIdx.x;
    if (i < HID * HID) {
        int r = i >> 8;      // source row (k)
        int c = i & 255;     // source col (j)
        g_W1T[c * HID + r] = W1[i];
        g_W2T[c * HID + r] = W2[i];
        if (r < INF) g_W0T[c * INF + r] = W0[i];
    }
}

// ---- packed f32x2 helpers (sm_103a) ----
__device__ __forceinline__ ull pk2(float x) {
    ull d; asm("mov.b64 %0, {%1, %1};" : "=l"(d) : "f"(x)); return d;
}
__device__ __forceinline__ ull ff2(ull a, ull b, ull c) {
    ull d; asm("fma.rn.f32x2 %0, %1, %2, %3;" : "=l"(d) : "l"(a), "l"(b), "l"(c)); return d;
}
__device__ __forceinline__ float2 upk(ull a) {
    float2 r; asm("mov.b64 {%0, %1}, %2;" : "=f"(r.x), "=f"(r.y) : "l"(a)); return r;
}

// acc[p][j]: f32x2 lanes = samples (s0+2p, s0+2p+1), feature f2+j.
// inT: feature-major activations [K][TS] (broadcast LDS.128 pairs).
// W:   rows k, feature-contiguous (coalesced LDG.64 across lanes).
__device__ __forceinline__ void mmT(ull acc[4][2],
                                    const float* inT,
                                    const float* __restrict__ W,
                                    int K, int wst, int f2, int s0)
{
    #pragma unroll 4
    for (int k = 0; k < K; k++) {
        float2 w = *(const float2*)(W + k * wst + f2);
        ull w0 = pk2(w.x), w1 = pk2(w.y);
        const float* hp = inT + k * TS + s0;
        ulonglong2 hA = *(const ulonglong2*)(hp);
        ulonglong2 hB = *(const ulonglong2*)(hp + 4);
        acc[0][0] = ff2(hA.x, w0, acc[0][0]);  acc[0][1] = ff2(hA.x, w1, acc[0][1]);
        acc[1][0] = ff2(hA.y, w0, acc[1][0]);  acc[1][1] = ff2(hA.y, w1, acc[1][1]);
        acc[2][0] = ff2(hB.x, w0, acc[2][0]);  acc[2][1] = ff2(hB.x, w1, acc[2][1]);
        acc[3][0] = ff2(hB.y, w0, acc[3][0]);  acc[3][1] = ff2(hB.y, w1, acc[3][1]);
    }
}

// fast softplus + sigmoid
__device__ __forceinline__ void act2(float a, float& sp, float& sg) {
    float e = __expf(-fabsf(a));
    float d = 1.0f + e;
    sp = fmaxf(a, 0.f) + __logf(d);
    sg = (a >= 0.f) ? __fdividef(1.0f, d) : __fdividef(e, d);
}

__global__ __launch_bounds__(NTHR, 1)
void chnn_kernel(const float* __restrict__ z,
                 const float* __restrict__ m_params,
                 const float* __restrict__ W0, const float* __restrict__ b0,
                 const float* __restrict__ W1, const float* __restrict__ b1,
                 const float* __restrict__ W2, const float* __restrict__ b2,
                 const float* __restrict__ W3,
                 float* __restrict__ out)
{
    extern __shared__ float sm[];
    float* zT   = sm;                  // ZDIM*TS = 4608 (feature-major z; staging later)
    float* bufA = zT + ZDIM * TS;      // HID*TS  = 9216
    float* bufB = bufA + HID * TS;     // 9216
    float* gbuf = bufB + HID * TS;     // TB*GST  = 2176
    float* invm = gbuf + TB * GST;     // 32

    const int tid = threadIdx.x;
    const int blk = blockIdx.x;
    const int f2  = (tid & 127) * 2;   // 2 consecutive features
    const int s0  = (tid >> 7) * 8;    // 8 samples (4 f32x2 pairs)

    // load z transposed: zT[c][s]
    const float* zg = z + (size_t)blk * TB * ZDIM;
    for (int i = tid; i < TB * ZDIM; i += NTHR) {
        int s = i >> 7, c = i & 127;
        zT[c * TS + s] = zg[i];
    }
    if (tid < NND) invm[tid] = __expf(-m_params[tid]);
    __syncthreads();

    float sg0[8][2], sg1[8][2];   // register-resident sigmoids
    ull acc[4][2];

    // ============ L0: a0 = r @ W0 + b0 ; h0 -> bufA, sig0 -> regs ============
    {
        float2 bb = *(const float2*)(b0 + f2);
        ull bd0 = pk2(bb.x), bd1 = pk2(bb.y);
        #pragma unroll
        for (int p = 0; p < 4; p++) { acc[p][0] = bd0; acc[p][1] = bd1; }
        mmT(acc, zT, W0, INF, HID, f2, s0);
        float hh[8][2];
        #pragma unroll
        for (int p = 0; p < 4; p++)
            #pragma unroll
            for (int j = 0; j < 2; j++) {
                float2 u = upk(acc[p][j]);
                act2(u.x, hh[2*p][j],   sg0[2*p][j]);
                act2(u.y, hh[2*p+1][j], sg0[2*p+1][j]);
            }
        #pragma unroll
        for (int j = 0; j < 2; j++) {
            float* dst = bufA + (f2 + j) * TS + s0;
            *(float4*)(dst)     = make_float4(hh[0][j], hh[1][j], hh[2][j], hh[3][j]);
            *(float4*)(dst + 4) = make_float4(hh[4][j], hh[5][j], hh[6][j], hh[7][j]);
        }
    }
    __syncthreads();

    // ============ L1: h1 -> bufB, sig1 -> regs ============
    {
        float2 bb = *(const float2*)(b1 + f2);
        ull bd0 = pk2(bb.x), bd1 = pk2(bb.y);
        #pragma unroll
        for (int p = 0; p < 4; p++) { acc[p][0] = bd0; acc[p][1] = bd1; }
        mmT(acc, bufA, W1, HID, HID, f2, s0);
        float hh[8][2];
        #pragma unroll
        for (int p = 0; p < 4; p++)
            #pragma unroll
            for (int j = 0; j < 2; j++) {
                float2 u = upk(acc[p][j]);
                act2(u.x, hh[2*p][j],   sg1[2*p][j]);
                act2(u.y, hh[2*p+1][j], sg1[2*p+1][j]);
            }
        #pragma unroll
        for (int j = 0; j < 2; j++) {
            float* dst = bufB + (f2 + j) * TS + s0;
            *(float4*)(dst)     = make_float4(hh[0][j], hh[1][j], hh[2][j], hh[3][j]);
            *(float4*)(dst + 4) = make_float4(hh[4][j], hh[5][j], hh[6][j], hh[7][j]);
        }
    }
    __syncthreads();

    // ============ L2: a2 -> da2 = W3[f]*sigmoid(a2) -> bufA (h0 dead) ============
    {
        float2 bb = *(const float2*)(b2 + f2);
        ull bd0 = pk2(bb.x), bd1 = pk2(bb.y);
        #pragma unroll
        for (int p = 0; p < 4; p++) { acc[p][0] = bd0; acc[p][1] = bd1; }
        mmT(acc, bufB, W2, HID, HID, f2, s0);
        float2 w3 = *(const float2*)(W3 + f2);
        float wj[2] = {w3.x, w3.y};
        float dd[8][2];
        #pragma unroll
        for (int p = 0; p < 4; p++)
            #pragma unroll
            for (int j = 0; j < 2; j++) {
                float2 u = upk(acc[p][j]);
                float e0 = __expf(-fabsf(u.x)); float q0 = 1.0f + e0;
                float s0v = (u.x >= 0.f) ? __fdividef(1.0f, q0) : __fdividef(e0, q0);
                float e1 = __expf(-fabsf(u.y)); float q1 = 1.0f + e1;
                float s1v = (u.y >= 0.f) ? __fdividef(1.0f, q1) : __fdividef(e1, q1);
                dd[2*p][j]   = wj[j] * s0v;
                dd[2*p+1][j] = wj[j] * s1v;
            }
        #pragma unroll
        for (int j = 0; j < 2; j++) {
            float* dst = bufA + (f2 + j) * TS + s0;
            *(float4*)(dst)     = make_float4(dd[0][j], dd[1][j], dd[2][j], dd[3][j]);
            *(float4*)(dst + 4) = make_float4(dd[4][j], dd[5][j], dd[6][j], dd[7][j]);
        }
    }
    __syncthreads();

    // ============ B1: dh1 = da2 @ W2^T ; da1 = dh1*sig1(regs) -> bufB (h1 dead) ============
    {
        #pragma unroll
        for (int p = 0; p < 4; p++) { acc[p][0] = 0ull; acc[p][1] = 0ull; }
        mmT(acc, bufA, g_W2T, HID, HID, f2, s0);
        float dd[8][2];
        #pragma unroll
        for (int p = 0; p < 4; p++)
            #pragma unroll
            for (int j = 0; j < 2; j++) {
                float2 u = upk(acc[p][j]);
                dd[2*p][j]   = u.x * sg1[2*p][j];
                dd[2*p+1][j] = u.y * sg1[2*p+1][j];
            }
        #pragma unroll
        for (int j = 0; j < 2; j++) {
            float* dst = bufB + (f2 + j) * TS + s0;
            *(float4*)(dst)     = make_float4(dd[0][j], dd[1][j], dd[2][j], dd[3][j]);
            *(float4*)(dst + 4) = make_float4(dd[4][j], dd[5][j], dd[6][j], dd[7][j]);
        }
    }
    __syncthreads();

    // ============ B2: dh0 = da1 @ W1^T ; da0 = dh0*sig0(regs) -> bufA (da2 dead) ============
    {
        #pragma unroll
        for (int p = 0; p < 4; p++) { acc[p][0] = 0ull; acc[p][1] = 0ull; }
        mmT(acc, bufB, g_W1T, HID, HID, f2, s0);
        float dd[8][2];
        #pragma unroll
        for (int p = 0; p < 4; p++)
            #pragma unroll
            for (int j = 0; j < 2; j++) {
                float2 u = upk(acc[p][j]);
                dd[2*p][j]   = u.x * sg0[2*p][j];
                dd[2*p+1][j] = u.y * sg0[2*p+1][j];
            }
        #pragma unroll
        for (int j = 0; j < 2; j++) {
            float* dst = bufA + (f2 + j) * TS + s0;
            *(float4*)(dst)     = make_float4(dd[0][j], dd[1][j], dd[2][j], dd[3][j]);
            *(float4*)(dst + 4) = make_float4(dd[4][j], dd[5][j], dd[6][j], dd[7][j]);
        }
    }
    __syncthreads();

    // ============ B3: g = da0 @ W0^T (256 -> 64) -> gbuf (sample-major) ============
    // thread: 2 features (fb), 2 samples (sb pair in f32x2 lanes)
    {
        const int fb = (tid & 31) * 2;
        const int sb = (tid >> 5) * 2;
        ull a0 = 0ull, a1 = 0ull;
        #pragma unroll 4
        for (int j = 0; j < HID; j++) {
            float2 w = *(const float2*)(g_W0T + j * INF + fb);
            ull hp = *(const ull*)(bufA + j * TS + sb);
            a0 = ff2(hp, pk2(w.x), a0);
            a1 = ff2(hp, pk2(w.y), a1);
        }
        float2 u0 = upk(a0), u1 = upk(a1);
        gbuf[sb * GST + fb]           = u0.x;
        gbuf[sb * GST + fb + 1]       = u1.x;
        gbuf[(sb + 1) * GST + fb]     = u0.y;
        gbuf[(sb + 1) * GST + fb + 1] = u1.y;
    }
    __syncthreads();

    // ============ constraint solve: 1 thread / sample ============
    // A = [[0,G],[-G,S]] with G tridiagonal SPD, S tridiagonal antisym. Two Thomas solves.
    float* scr = bufA;  // bufA+bufB = 18432 floats free
    float* Ex  = scr + 0  * NND * TB;
    float* Ey  = scr + 1  * NND * TB;
    float* Edx = scr + 2  * NND * TB;
    float* Edy = scr + 3  * NND * TB;
    float* Vx  = scr + 4  * NND * TB;
    float* Vy  = scr + 5  * NND * TB;
    float* Dd  = scr + 6  * NND * TB;
    float* Du  = scr + 7  * NND * TB;
    float* Dl  = scr + 8  * NND * TB;
    float* So  = scr + 9  * NND * TB;
    float* R0  = scr + 10 * NND * TB;   // b0 -> x1
    float* R1  = scr + 11 * NND * TB;   // b1 -> y -> x0

    if (tid < TB) {
        const int s = tid;
        #define ZTV(x) zT[(x) * TS + s]

        // build E_c, Edot_c, v
        {
            float prx = ZTV(0), pry = ZTV(1);
            float im  = invm[0];
            float pvx = ZTV(64) * im, pvy = ZTV(65) * im;
            Ex[s]  = 2.f * prx;  Ey[s]  = 2.f * pry;
            Edx[s] = 2.f * pvx;  Edy[s] = 2.f * pvy;
            Vx[s] = pvx; Vy[s] = pvy;
            for (int c = 1; c < NND; c++) {
                float rx = ZTV(2*c), ry = ZTV(2*c+1);
                float imc = invm[c];
                float vx = ZTV(64 + 2*c) * imc, vy = ZTV(65 + 2*c) * imc;
                Ex[c*TB+s]  = 2.f*(prx - rx);  Ey[c*TB+s]  = 2.f*(pry - ry);
                Edx[c*TB+s] = 2.f*(pvx - vx);  Edy[c*TB+s] = 2.f*(pvy - vy);
                Vx[c*TB+s] = vx; Vy[c*TB+s] = vy;
                prx = rx; pry = ry; pvx = vx; pvy = vy;
            }
        }
        // tridiagonal G, S offdiag, rhs
        {
            float e0x = Ex[s],  e0y = Ey[s];
            float d0x = Edx[s], d0y = Edy[s];
            float v0x = Vx[s],  v0y = Vy[s];
            float im0 = invm[0];
            float e1x = Ex[TB+s],  e1y = Ey[TB+s];
            float d1x = Edx[TB+s], d1y = Edy[TB+s];
            Dd[s] = im0 * (e0x*e0x + e0y*e0y);
            Du[s] = im0 * (e0x*e1x + e0y*e1y);
            So[s] = im0 * (d0x*e1x + d0y*e1y - d1x*e0x - d1y*e0y);
            R0[s] = e0x*v0x + e0y*v0y;
            float g0x = gbuf[s*GST + 0], g0y = gbuf[s*GST + 1];
            R1[s] = d0x*v0x + d0y*v0y - im0*(e0x*g0x + e0y*g0y);
            for (int c = 1; c < NND; c++) {
                float ecx = Ex[c*TB+s],  ecy = Ey[c*TB+s];
                float dcx = Edx[c*TB+s], dcy = Edy[c*TB+s];
                float imc = invm[c], imp = invm[c-1];
                Dd[c*TB+s] = (imp + imc) * (ecx*ecx + ecy*ecy);
                R0[c*TB+s] = 0.5f * (ecx*dcx + ecy*dcy);
                float gpx = gbuf[s*GST + 2*(c-1)], gpy = gbuf[s*GST + 2*(c-1)+1];
                float gcx = gbuf[s*GST + 2*c],     gcy = gbuf[s*GST + 2*c+1];
                R1[c*TB+s] = 0.5f*(dcx*dcx + dcy*dcy)
                           - (ecx*(imp*gpx - imc*gcx) + ecy*(imp*gpy - imc*gcy));
                if (c < NND - 1) {
                    float enx = Ex[(c+1)*TB+s],  eny = Ey[(c+1)*TB+s];
                    float dnx = Edx[(c+1)*TB+s], dny = Edy[(c+1)*TB+s];
                    Du[c*TB+s] = -imc * (ecx*enx + ecy*eny);
                    So[c*TB+s] =  imc * (dnx*ecx + dny*ecy - dcx*enx - dcy*eny);
                }
            }
        }
        // Thomas factorization of G
        for (int c = 1; c < NND; c++) {
            float l = Du[(c-1)*TB+s] / Dd[(c-1)*TB+s];
            Dl[c*TB+s] = l;
            Dd[c*TB+s] = Dd[c*TB+s] - l * Du[(c-1)*TB+s];
        }
        // solve G x1 = b0
        for (int c = 1; c < NND; c++)
            R0[c*TB+s] -= Dl[c*TB+s] * R0[(c-1)*TB+s];
        R0[(NND-1)*TB+s] /= Dd[(NND-1)*TB+s];
        for (int c = NND - 2; c >= 0; c--)
            R0[c*TB+s] = (R0[c*TB+s] - Du[c*TB+s] * R0[(c+1)*TB+s]) / Dd[c*TB+s];
        // y = S x1 - b1
        R1[s] = So[s] * R0[TB+s] - R1[s];
        for (int c = 1; c < NND - 1; c++)
            R1[c*TB+s] = So[c*TB+s]*R0[(c+1)*TB+s] - So[(c-1)*TB+s]*R0[(c-1)*TB+s] - R1[c*TB+s];
        R1[(NND-1)*TB+s] = -So[(NND-2)*TB+s]*R0[(NND-2)*TB+s] - R1[(NND-1)*TB+s];
        // solve G x0 = y
        for (int c = 1; c < NND; c++)
            R1[c*TB+s] -= Dl[c*TB+s] * R1[(c-1)*TB+s];
        R1[(NND-1)*TB+s] /= Dd[(NND-1)*TB+s];
        for (int c = NND - 2; c >= 0; c--)
            R1[c*TB+s] = (R1[c*TB+s] - Du[c*TB+s]*R1[(c+1)*TB+s]) / Dd[c*TB+s];

        // outputs staged into own zT column (race-free per-sample)
        for (int i = 0; i < NND; i++) {
            float eix = Ex[i*TB+s],  eiy = Ey[i*TB+s];
            float dix = Edx[i*TB+s], diy = Edy[i*TB+s];
            float x1i = R0[i*TB+s],  x0i = R1[i*TB+s];
            float p1x, p1y, p0x, p0y, pdx, pdy;
            if (i == 0) {
                float enx = Ex[TB+s],  eny = Ey[TB+s];
                float dnx = Edx[TB+s], dny = Edy[TB+s];
                float x1n = R0[TB+s],  x0n = R1[TB+s];
                p1x = eix*x1i + enx*x1n;  p1y = eiy*x1i + eny*x1n;
                p0x = eix*x0i + enx*x0n;  p0y = eiy*x0i + eny*x0n;
                pdx = dix*x1i + dnx*x1n;  pdy = diy*x1i + dny*x1n;
            } else if (i < NND - 1) {
                float enx = Ex[(i+1)*TB+s],  eny = Ey[(i+1)*TB+s];
                float dnx = Edx[(i+1)*TB+s], dny = Edy[(i+1)*TB+s];
                float x1n = R0[(i+1)*TB+s],  x0n = R1[(i+1)*TB+s];
                p1x = -eix*x1i + enx*x1n;  p1y = -eiy*x1i + eny*x1n;
                p0x = -eix*x0i + enx*x0n;  p0y = -eiy*x0i + eny*x0n;
                pdx = -dix*x1i + dnx*x1n;  pdy = -diy*x1i + dny*x1n;
            } else {
                p1x = -eix*x1i; p1y = -eiy*x1i;
                p0x = -eix*x0i; p0y = -eiy*x0i;
                pdx = -dix*x1i; pdy = -diy*x1i;
            }
            float imi = invm[i];
            float gx = gbuf[s*GST + 2*i], gy = gbuf[s*GST + 2*i + 1];
            ZTV(2*i)        = Vx[i*TB+s] - imi * p1x;
            ZTV(2*i + 1)    = Vy[i*TB+s] - imi * p1y;
            ZTV(64 + 2*i)   = -gx + p0x + pdx;
            ZTV(64 + 2*i+1) = -gy + p0y + pdy;
        }
        #undef ZTV
    }
    __syncthreads();

    // coalesced store from zT staging
    float* outg = out + (size_t)blk * TB * ZDIM;
    for (int i = tid; i < TB * ZDIM; i += NTHR) {
        int s = i >> 7, c = i & 127;
        outg[i] = zT[c * TS + s];
    }
}

extern "C" void kernel_launch(void* const* d_in, const int* in_sizes, int n_in,
                              void* d_out, int out_size)
{
    (void)in_sizes; (void)n_in; (void)out_size;
    const float* z  = (const float*)d_in[1];
    const float* mp = (const float*)d_in[2];
    const float* W0 = (const float*)d_in[3];
    const float* b0 = (const float*)d_in[4];
    const float* W1 = (const float*)d_in[5];
    const float* b1 = (const float*)d_in[6];
    const float* W2 = (const float*)d_in[7];
    const float* b2 = (const float*)d_in[8];
    const float* W3 = (const float*)d_in[9];
    float* out = (float*)d_out;

    transpose_k<<<(HID * HID + 255) / 256, 256>>>(W0, W1, W2);

    size_t smem = (size_t)(ZDIM * TS + 2 * HID * TS + TB * GST + 32) * sizeof(float);
    cudaFuncSetAttribute(chnn_kernel, cudaFuncAttributeMaxDynamicSharedMemorySize, (int)smem);
    chnn_kernel<<<NCTA, NTHR, smem>>>(z, mp, W0, b0, W1, b1, W2, b2, W3, out);
}

// round 5
// speedup vs baseline: 3.7633x; 1.2414x over previous
#include <cuda_runtime.h>
#include <math.h>

#define BSZ   4096
#define NND   32
#define ZDIM  128
#define HID   256
#define INF   64
#define TB    32
#define NTHR  512
#define NCTA  (BSZ / TB)

#define ZST   132   // padded stride for z tile (132*4B = 33*16B -> float4-aligned rows)
#define GST   65    // padded stride for dV/dr tile
#define SST   129   // padded stride for output stage

typedef unsigned long long ull;

// transposed weights (device scratch; rebuilt every launch, deterministic)
__device__ __align__(16) float g_W1T[HID * HID];
__device__ __align__(16) float g_W2T[HID * HID];
__device__ __align__(16) float g_W0T[HID * INF];

__global__ void transpose_k(const float* __restrict__ W0,
                            const float* __restrict__ W1,
                            const float* __restrict__ W2)
{
    int i = blockIdx.x * blockDim.x + threadIdx.x;
    if (i < HID * HID) {
        int r = i >> 8;      // source row (k)
        int c = i & 255;     // source col (j)
        g_W1T[c * HID + r] = W1[i];
        g_W2T[c * HID + r] = W2[i];
        if (r < INF) g_W0T[c * INF + r] = W0[i];
    }
}

// ---- packed f32x2 helpers (sm_103a) ----
__device__ __forceinline__ ull pk2(float x) {
    ull d; asm("mov.b64 %0, {%1, %1};" : "=l"(d) : "f"(x)); return d;
}
__device__ __forceinline__ ull ff2(ull a, ull b, ull c) {
    ull d; asm("fma.rn.f32x2 %0, %1, %2, %3;" : "=l"(d) : "l"(a), "l"(b), "l"(c)); return d;
}
__device__ __forceinline__ float2 upk(ull a) {
    float2 r; asm("mov.b64 {%0, %1}, %2;" : "=f"(r.x), "=f"(r.y) : "l"(a)); return r;
}

// one k-step: acc[i][:] += h[i].<c> * (w.x, w.y)
__device__ __forceinline__ void fma_step(ull acc[4][2], const float4 h[4], int c,
                                         const ulonglong2& w)
{
    #pragma unroll
    for (int i = 0; i < 4; i++) {
        float hv = (c == 0) ? h[i].x : (c == 1) ? h[i].y : (c == 2) ? h[i].z : h[i].w;
        ull hd = pk2(hv);
        acc[i][0] = ff2(hd, w.x, acc[i][0]);
        acc[i][1] = ff2(hd, w.y, acc[i][1]);
    }
}

// acc[i][jp] (+)= sum_k in[(s0+i)*istride + k] * W[k*HID + f4 + 2*jp + {0,1}]
// Software-pipelined: weight rows prefetched one half-block (k4) ahead so the
// L1/L2 latency of the LDG.128s is covered by the previous stage's FFMA2s.
__device__ __forceinline__ void mmv(ull acc[4][2],
                                    const float* in, int istride,
                                    const float* __restrict__ W, int K,
                                    int f4, int s0)
{
    const float* wp = W + f4;
    const float* ip = in + s0 * istride;

    // preload rows 0..3
    ulonglong2 wa0 = *(const ulonglong2*)(wp + 0 * HID);
    ulonglong2 wa1 = *(const ulonglong2*)(wp + 1 * HID);
    ulonglong2 wa2 = *(const ulonglong2*)(wp + 2 * HID);
    ulonglong2 wa3 = *(const ulonglong2*)(wp + 3 * HID);

    #pragma unroll 1
    for (int k8 = 0; k8 < K; k8 += 8) {
        // prefetch rows k8+4..k8+7 (always in range: K multiple of 8)
        const float* pb = wp + (k8 + 4) * HID;
        ulonglong2 wb0 = *(const ulonglong2*)(pb + 0 * HID);
        ulonglong2 wb1 = *(const ulonglong2*)(pb + 1 * HID);
        ulonglong2 wb2 = *(const ulonglong2*)(pb + 2 * HID);
        ulonglong2 wb3 = *(const ulonglong2*)(pb + 3 * HID);

        // stage A: k8..k8+3
        float4 hA[4];
        #pragma unroll
        for (int i = 0; i < 4; i++)
            hA[i] = *(const float4*)(ip + i * istride + k8);
        fma_step(acc, hA, 0, wa0);
        fma_step(acc, hA, 1, wa1);
        fma_step(acc, hA, 2, wa2);
        fma_step(acc, hA, 3, wa3);

        // prefetch rows k8+8..k8+11 for next iteration
        ulonglong2 na0 = wa0, na1 = wa1, na2 = wa2, na3 = wa3;
        if (k8 + 8 < K) {
            const float* pa = wp + (k8 + 8) * HID;
            na0 = *(const ulonglong2*)(pa + 0 * HID);
            na1 = *(const ulonglong2*)(pa + 1 * HID);
            na2 = *(const ulonglong2*)(pa + 2 * HID);
            na3 = *(const ulonglong2*)(pa + 3 * HID);
        }

        // stage B: k8+4..k8+7
        float4 hB[4];
        #pragma unroll
        for (int i = 0; i < 4; i++)
            hB[i] = *(const float4*)(ip + i * istride + k8 + 4);
        fma_step(acc, hB, 0, wb0);
        fma_step(acc, hB, 1, wb1);
        fma_step(acc, hB, 2, wb2);
        fma_step(acc, hB, 3, wb3);

        wa0 = na0; wa1 = na1; wa2 = na2; wa3 = na3;
    }
}

// fast softplus + sigmoid (validated: rel_err unchanged at ~3.2e-6)
__device__ __forceinline__ void act2(float a, float& sp, float& sg) {
    float e = __expf(-fabsf(a));
    float d = 1.0f + e;
    sp = fmaxf(a, 0.f) + __logf(d);
    sg = (a >= 0.f) ? __fdividef(1.0f, d) : __fdividef(e, d);
}

__global__ __launch_bounds__(NTHR, 1)
void chnn_kernel(const float* __restrict__ z,
                 const float* __restrict__ m_params,
                 const float* __restrict__ W0, const float* __restrict__ b0,
                 const float* __restrict__ W1, const float* __restrict__ b1,
                 const float* __restrict__ W2, const float* __restrict__ b2,
                 const float* __restrict__ W3,
                 float* __restrict__ out)
{
    extern __shared__ float sm[];
    float* zbuf = sm;                       // TB*ZST  = 4224
    float* bufA = zbuf + TB * ZST;          // TB*HID  = 8192
    float* bufB = bufA + TB * HID;          // 8192
    float* sig0 = bufB + TB * HID;          // 8192
    float* sig1 = sig0 + TB * HID;          // 8192
    float* gbuf = sig1 + TB * HID;          // TB*GST  = 2080
    float* invm = gbuf + TB * GST;          // 32

    const int tid  = threadIdx.x;
    const int blk  = blockIdx.x;
    const int f4   = (tid & 63) * 4;        // 4 consecutive features per thread
    const int s0   = (tid >> 6) * 4;        // 4 samples per thread

    // cooperative load of z tile (padded rows)
    const float* zg = z + (size_t)blk * TB * ZDIM;
    for (int i = tid; i < TB * ZDIM; i += NTHR)
        zbuf[(i >> 7) * ZST + (i & 127)] = zg[i];
    if (tid < NND) invm[tid] = __expf(-m_params[tid]);
    __syncthreads();

    ull acc[4][2];

    // ============ L0: a0 = r @ W0 + b0 ; h0 -> bufA, sig0 ============
    {
        const ulonglong2 bv = *(const ulonglong2*)(b0 + f4);
        #pragma unroll
        for (int i = 0; i < 4; i++) { acc[i][0] = bv.x; acc[i][1] = bv.y; }
        mmv(acc, zbuf, ZST, W0, INF, f4, s0);
        #pragma unroll
        for (int i = 0; i < 4; i++) {
            float2 a01 = upk(acc[i][0]), a23 = upk(acc[i][1]);
            float av[4] = {a01.x, a01.y, a23.x, a23.y};
            float hb[4], sb[4];
            #pragma unroll
            for (int j = 0; j < 4; j++) act2(av[j], hb[j], sb[j]);
            int o = (s0 + i) * HID + f4;
            *(float4*)(bufA + o) = make_float4(hb[0], hb[1], hb[2], hb[3]);
            *(float4*)(sig0 + o) = make_float4(sb[0], sb[1], sb[2], sb[3]);
        }
    }
    __syncthreads();

    // ============ L1: h1 -> bufB, sig1 ============
    {
        const ulonglong2 bv = *(const ulonglong2*)(b1 + f4);
        #pragma unroll
        for (int i = 0; i < 4; i++) { acc[i][0] = bv.x; acc[i][1] = bv.y; }
        mmv(acc, bufA, HID, W1, HID, f4, s0);
        #pragma unroll
        for (int i = 0; i < 4; i++) {
            float2 a01 = upk(acc[i][0]), a23 = upk(acc[i][1]);
            float av[4] = {a01.x, a01.y, a23.x, a23.y};
            float hb[4], sb[4];
            #pragma unroll
            for (int j = 0; j < 4; j++) act2(av[j], hb[j], sb[j]);
            int o = (s0 + i) * HID + f4;
            *(float4*)(bufB + o) = make_float4(hb[0], hb[1], hb[2], hb[3]);
            *(float4*)(sig1 + o) = make_float4(sb[0], sb[1], sb[2], sb[3]);
        }
    }
    __syncthreads();

    // ============ L2 fused with da2 = W3[f]*sigmoid(a2) -> bufA ============
    {
        const ulonglong2 bv = *(const ulonglong2*)(b2 + f4);
        #pragma unroll
        for (int i = 0; i < 4; i++) { acc[i][0] = bv.x; acc[i][1] = bv.y; }
        mmv(acc, bufB, HID, W2, HID, f4, s0);
        const float4 w3v = *(const float4*)(W3 + f4);
        const float wv[4] = {w3v.x, w3v.y, w3v.z, w3v.w};
        #pragma unroll
        for (int i = 0; i < 4; i++) {
            float2 a01 = upk(acc[i][0]), a23 = upk(acc[i][1]);
            float av[4] = {a01.x, a01.y, a23.x, a23.y};
            float db[4];
            #pragma unroll
            for (int j = 0; j < 4; j++) {
                float a = av[j];
                float e = __expf(-fabsf(a));
                float d = 1.0f + e;
                float sg = (a >= 0.f) ? __fdividef(1.0f, d) : __fdividef(e, d);
                db[j] = wv[j] * sg;
            }
            *(float4*)(bufA + (s0 + i) * HID + f4) = make_float4(db[0], db[1], db[2], db[3]);
        }
    }
    __syncthreads();

    // ============ B1: dh1 = da2 @ W2^T ; da1 = dh1*sig1 -> bufB ============
    {
        #pragma unroll
        for (int i = 0; i < 4; i++) { acc[i][0] = 0ull; acc[i][1] = 0ull; }
        mmv(acc, bufA, HID, g_W2T, HID, f4, s0);
        #pragma unroll
        for (int i = 0; i < 4; i++) {
            int o = (s0 + i) * HID + f4;
            float4 sg4 = *(const float4*)(sig1 + o);
            float2 a01 = upk(acc[i][0]), a23 = upk(acc[i][1]);
            *(float4*)(bufB + o) = make_float4(a01.x * sg4.x, a01.y * sg4.y,
                                               a23.x * sg4.z, a23.y * sg4.w);
        }
    }
    __syncthreads();

    // ============ B2: dh0 = da1 @ W1^T ; da0 = dh0*sig0 -> bufA ============
    {
        #pragma unroll
        for (int i = 0; i < 4; i++) { acc[i][0] = 0ull; acc[i][1] = 0ull; }
        mmv(acc, bufB, HID, g_W1T, HID, f4, s0);
        #pragma unroll
        for (int i = 0; i < 4; i++) {
            int o = (s0 + i) * HID + f4;
            float4 sg4 = *(const float4*)(sig0 + o);
            float2 a01 = upk(acc[i][0]), a23 = upk(acc[i][1]);
            *(float4*)(bufA + o) = make_float4(a01.x * sg4.x, a01.y * sg4.y,
                                               a23.x * sg4.z, a23.y * sg4.w);
        }
    }
    __syncthreads();

    // ============ B3: g = dV/dr = da0 @ W0^T (256 -> 64) -> gbuf ============
    {
        float a8[8];
        #pragma unroll
        for (int i = 0; i < 8; i++) a8[i] = 0.f;
        const int m = (tid & 63);
        const int sb = (tid >> 6) * 4;   // same 4 samples, plus neighbor group shares
        // each thread: feature m, 8 samples starting at (tid>>6)*4 rounded to 8-group
        const int s8 = (sb & ~7);
        const int half = (sb & 4) ? 1 : 0;
        // threads with same m and adjacent groups both compute; keep R1 structure:
        // recompute full 8-sample tile per 64-thread group pair is wasteful; instead
        // do 8 samples per thread using group base s8 only when half==0, else skip.
        // Simpler: every thread computes 4 samples (its own group) for feature m.
        (void)s8; (void)half;
        #pragma unroll 4
        for (int k = 0; k < HID; k++) {
            float w = g_W0T[k * INF + m];
            #pragma unroll
            for (int i = 0; i < 4; i++)
                a8[i] = fmaf(bufA[(sb + i) * HID + k], w, a8[i]);
        }
        #pragma unroll
        for (int i = 0; i < 4; i++) gbuf[(sb + i) * GST + m] = a8[i];
    }
    __syncthreads();

    // ============ constraint solve: 1 thread / sample ============
    // A = [[0,G],[-G,S]] with G = E^T M^-1 E tridiagonal SPD (32x32),
    // S tridiagonal antisymmetric. Two Thomas solves.
    float* scr = sig0;  // sig0+sig1 (16384 floats) free now
    float* Ex  = scr + 0  * NND * TB;
    float* Ey  = scr + 1  * NND * TB;
    float* Edx = scr + 2  * NND * TB;
    float* Edy = scr + 3  * NND * TB;
    float* Vx  = scr + 4  * NND * TB;
    float* Vy  = scr + 5  * NND * TB;
    float* Dd  = scr + 6  * NND * TB;
    float* Du  = scr + 7  * NND * TB;
    float* Dl  = scr + 8  * NND * TB;
    float* So  = scr + 9  * NND * TB;
    float* R0  = scr + 10 * NND * TB;   // b0 -> x1
    float* R1  = scr + 11 * NND * TB;   // b1 -> y -> x0

    if (tid < TB) {
        const int s = tid;
        const float* zr = zbuf + s * ZST;

        // build E_c, Edot_c, v  (E_0 = 2 r_0; E_c = 2(r_{c-1}-r_c))
        {
            float prx = zr[0], pry = zr[1];
            float im  = invm[0];
            float pvx = zr[64] * im, pvy = zr[65] * im;
            Ex[s]  = 2.f * prx;  Ey[s]  = 2.f * pry;
            Edx[s] = 2.f * pvx;  Edy[s] = 2.f * pvy;
            Vx[s] = pvx; Vy[s] = pvy;
            for (int c = 1; c < NND; c++) {
                float rx = zr[2*c], ry = zr[2*c+1];
                float imc = invm[c];
                float vx = zr[64 + 2*c] * imc, vy = zr[65 + 2*c] * imc;
                Ex[c*TB+s]  = 2.f*(prx - rx);  Ey[c*TB+s]  = 2.f*(pry - ry);
                Edx[c*TB+s] = 2.f*(pvx - vx);  Edy[c*TB+s] = 2.f*(pvy - vy);
                Vx[c*TB+s] = vx; Vy[c*TB+s] = vy;
                prx = rx; pry = ry; pvx = vx; pvy = vy;
            }
        }
        // tridiagonal G (Dd diag, Du upper), S offdiag (So), rhs b0 (R0), b1 (R1)
        {
            float e0x = Ex[s],  e0y = Ey[s];
            float d0x = Edx[s], d0y = Edy[s];
            float v0x = Vx[s],  v0y = Vy[s];
            float im0 = invm[0];
            float e1x = Ex[TB+s],  e1y = Ey[TB+s];
            float d1x = Edx[TB+s], d1y = Edy[TB+s];
            Dd[s] = im0 * (e0x*e0x + e0y*e0y);
            Du[s] = im0 * (e0x*e1x + e0y*e1y);
            So[s] = im0 * (d0x*e1x + d0y*e1y - d1x*e0x - d1y*e0y);
            R0[s] = e0x*v0x + e0y*v0y;
            float g0x = gbuf[s*GST + 0], g0y = gbuf[s*GST + 1];
            R1[s] = d0x*v0x + d0y*v0y - im0*(e0x*g0x + e0y*g0y);
            for (int c = 1; c < NND; c++) {
                float ecx = Ex[c*TB+s],  ecy = Ey[c*TB+s];
                float dcx = Edx[c*TB+s], dcy = Edy[c*TB+s];
                float imc = invm[c], imp = invm[c-1];
                Dd[c*TB+s] = (imp + imc) * (ecx*ecx + ecy*ecy);
                R0[c*TB+s] = 0.5f * (ecx*dcx + ecy*dcy);
                float gpx = gbuf[s*GST + 2*(c-1)], gpy = gbuf[s*GST + 2*(c-1)+1];
                float gcx = gbuf[s*GST + 2*c],     gcy = gbuf[s*GST + 2*c+1];
                R1[c*TB+s] = 0.5f*(dcx*dcx + dcy*dcy)
                           - (ecx*(imp*gpx - imc*gcx) + ecy*(imp*gpy - imc*gcy));
                if (c < NND - 1) {
                    float enx = Ex[(c+1)*TB+s],  eny = Ey[(c+1)*TB+s];
                    float dnx = Edx[(c+1)*TB+s], dny = Edy[(c+1)*TB+s];
                    Du[c*TB+s] = -imc * (ecx*enx + ecy*eny);
                    So[c*TB+s] =  imc * (dnx*ecx + dny*ecy - dcx*enx - dcy*eny);
                }
            }
        }
        // Thomas factorization of G
        for (int c = 1; c < NND; c++) {
            float l = Du[(c-1)*TB+s] / Dd[(c-1)*TB+s];
            Dl[c*TB+s] = l;
            Dd[c*TB+s] = Dd[c*TB+s] - l * Du[(c-1)*TB+s];
        }
        // solve G x1 = b0 (in place in R0)
        for (int c = 1; c < NND; c++)
            R0[c*TB+s] -= Dl[c*TB+s] * R0[(c-1)*TB+s];
        R0[(NND-1)*TB+s] /= Dd[(NND-1)*TB+s];
        for (int c = NND - 2; c >= 0; c--)
            R0[c*TB+s] = (R0[c*TB+s] - Du[c*TB+s] * R0[(c+1)*TB+s]) / Dd[c*TB+s];
        // y = S x1 - b1 (into R1)
        R1[s] = So[s] * R0[TB+s] - R1[s];
        for (int c = 1; c < NND - 1; c++)
            R1[c*TB+s] = So[c*TB+s]*R0[(c+1)*TB+s] - So[(c-1)*TB+s]*R0[(c-1)*TB+s] - R1[c*TB+s];
        R1[(NND-1)*TB+s] = -So[(NND-2)*TB+s]*R0[(NND-2)*TB+s] - R1[(NND-1)*TB+s];
        // solve G x0 = y (in place in R1)
        for (int c = 1; c < NND; c++)
            R1[c*TB+s] -= Dl[c*TB+s] * R1[(c-1)*TB+s];
        R1[(NND-1)*TB+s] /= Dd[(NND-1)*TB+s];
        for (int c = NND - 2; c >= 0; c--)
            R1[c*TB+s] = (R1[c*TB+s] - Du[c*TB+s]*R1[(c+1)*TB+s]) / Dd[c*TB+s];

        // output: out_r = v - M^-1 (E x1);  out_p = -g + (E x0) + (Edot x1)
        float* st = bufB + s * SST;
        for (int i = 0; i < NND; i++) {
            float eix = Ex[i*TB+s],  eiy = Ey[i*TB+s];
            float dix = Edx[i*TB+s], diy = Edy[i*TB+s];
            float x1i = R0[i*TB+s],  x0i = R1[i*TB+s];
            float p1x, p1y, p0x, p0y, pdx, pdy;
            if (i == 0) {
                float enx = Ex[TB+s],  eny = Ey[TB+s];
                float dnx = Edx[TB+s], dny = Edy[TB+s];
                float x1n = R0[TB+s],  x0n = R1[TB+s];
                p1x = eix*x1i + enx*x1n;  p1y = eiy*x1i + eny*x1n;
                p0x = eix*x0i + enx*x0n;  p0y = eiy*x0i + eny*x0n;
                pdx = dix*x1i + dnx*x1n;  pdy = diy*x1i + dny*x1n;
            } else if (i < NND - 1) {
                float enx = Ex[(i+1)*TB+s],  eny = Ey[(i+1)*TB+s];
                float dnx = Edx[(i+1)*TB+s], dny = Edy[(i+1)*TB+s];
                float x1n = R0[(i+1)*TB+s],  x0n = R1[(i+1)*TB+s];
                p1x = -eix*x1i + enx*x1n;  p1y = -eiy*x1i + eny*x1n;
                p0x = -eix*x0i + enx*x0n;  p0y = -eiy*x0i + eny*x0n;
                pdx = -dix*x1i + dnx*x1n;  pdy = -diy*x1i + dny*x1n;
            } else {
                p1x = -eix*x1i; p1y = -eiy*x1i;
                p0x = -eix*x0i; p0y = -eiy*x0i;
                pdx = -dix*x1i; pdy = -diy*x1i;
            }
            float imi = invm[i];
            st[2*i]     = Vx[i*TB+s] - imi * p1x;
            st[2*i + 1] = Vy[i*TB+s] - imi * p1y;
            float gx = gbuf[s*GST + 2*i], gy = gbuf[s*GST + 2*i + 1];
            st[64 + 2*i]     = -gx + p0x + pdx;
            st[64 + 2*i + 1] = -gy + p0y + pdy;
        }
    }
    __syncthreads();

    // coalesced store of staged output
    float* outg = out + (size_t)blk * TB * ZDIM;
    for (int i = tid; i < TB * ZDIM; i += NTHR)
        outg[i] = bufB[(i >> 7) * SST + (i & 127)];
}

extern "C" void kernel_launch(void* const* d_in, const int* in_sizes, int n_in,
                              void* d_out, int out_size)
{
    (void)in_sizes; (void)n_in; (void)out_size;
    const float* z  = (const float*)d_in[1];
    const float* mp = (const float*)d_in[2];
    const float* W0 = (const float*)d_in[3];
    const float* b0 = (const float*)d_in[4];
    const float* W1 = (const float*)d_in[5];
    const float* b1 = (const float*)d_in[6];
    const float* W2 = (const float*)d_in[7];
    const float* b2 = (const float*)d_in[8];
    const float* W3 = (const float*)d_in[9];
    float* out = (float*)d_out;

    transpose_k<<<(HID * HID + 255) / 256, 256>>>(W0, W1, W2);

    size_t smem = (size_t)(TB * ZST + 4 * TB * HID + TB * GST + 32) * sizeof(float);
    cudaFuncSetAttribute(chnn_kernel, cudaFuncAttributeMaxDynamicSharedMemorySize, (int)smem);
    chnn_kernel<<<NCTA, NTHR, smem>>>(z, mp, W0, b0, W1, b1, W2, b2, W3, out);
}

// round 7
// speedup vs baseline: 8.0876x; 2.1491x over previous
#include <cuda_runtime.h>
#include <cuda_bf16.h>
#include <stdint.h>
#include <math.h>

#define BSZ   4096
#define NND   32
#define ZDIM  128
#define HID   256
#define INF   64
#define TB    32
#define NTHR  512
#define NCTA  (BSZ / TB)

#define ZST   132
#define GST   65
#define SST   129
#define TROW  528           // bytes per activation-tile row (264 bf16, conflict-free)

// dynamic smem byte offsets
#define OFF_ZBUF  0         // 32*132 f = 16896 B
#define OFF_INVM  16896     // 32 f
#define OFF_GBUF  17024     // 32*65 f = 8320 B
#define OFF_T0H   25344     // 32*528 = 16896 B
#define OFF_T0L   42240
#define OFF_T1H   59136
#define OFF_T1L   76032
#define SMEM_BYTES 92928

// ---------------- pre-packed weight fragments (B operand of m16n8k16) ----
// layout [ntile][kstep][lane] : uint4 {h0, h1, l0, l1}
__device__ uint4 g_f0[32 * 4 * 32];    // L0 fwd: B[k][f] = W0[k][f], K=64
__device__ uint4 g_f1[32 * 16 * 32];   // L1 fwd: W1[k][f]
__device__ uint4 g_f2[32 * 16 * 32];   // L2 fwd: W2[k][f]
__device__ uint4 g_b2[32 * 16 * 32];   // B1 bwd: B[j][f] = W2[f][j]
__device__ uint4 g_b1[32 * 16 * 32];   // B2 bwd: B[j][f] = W1[f][j]
__device__ uint4 g_b0[8 * 16 * 32];    // B3 bwd: B[j][m] = W0[m][j], N=64

__device__ __forceinline__ uint32_t pkbf2(float lo, float hi) {
    uint32_t r;
    asm("cvt.rn.bf16x2.f32 %0, %1, %2;" : "=r"(r) : "f"(hi), "f"(lo));
    return r;
}
__device__ __forceinline__ float bfhi(float x) {
    return __bfloat162float(__float2bfloat16(x));
}
__device__ __forceinline__ uint4 mkfrag(float a0, float a1, float a2, float a3) {
    uint4 q;
    q.x = pkbf2(a0, a1);
    q.y = pkbf2(a2, a3);
    q.z = pkbf2(a0 - bfhi(a0), a1 - bfhi(a1));
    q.w = pkbf2(a2 - bfhi(a2), a3 - bfhi(a3));
    return q;
}

__global__ void prep_k(const float* __restrict__ W0,
                       const float* __restrict__ W1,
                       const float* __restrict__ W2)
{
    int i = blockIdx.x * blockDim.x + threadIdx.x;    // 0..16383
    if (i >= 16384) return;
    int lane = i & 31, ks = (i >> 5) & 15, nt = i >> 9;
    int t = lane & 3, g = lane >> 2;
    int k0 = ks * 16, f0 = nt * 8;

    // forward: B[k][n=f] = W[k][f]; b reg0 = (k0+2t, k0+2t+1), reg1 = (+8,+9), col f0+g
    g_f1[i] = mkfrag(W1[(k0+2*t)*HID + f0+g],   W1[(k0+2*t+1)*HID + f0+g],
                     W1[(k0+2*t+8)*HID + f0+g], W1[(k0+2*t+9)*HID + f0+g]);
    g_f2[i] = mkfrag(W2[(k0+2*t)*HID + f0+g],   W2[(k0+2*t+1)*HID + f0+g],
                     W2[(k0+2*t+8)*HID + f0+g], W2[(k0+2*t+9)*HID + f0+g]);
    // backward: B[k=j][n=f] = W[f][j]
    g_b1[i] = mkfrag(W1[(f0+g)*HID + k0+2*t],   W1[(f0+g)*HID + k0+2*t+1],
                     W1[(f0+g)*HID + k0+2*t+8], W1[(f0+g)*HID + k0+2*t+9]);
    g_b2[i] = mkfrag(W2[(f0+g)*HID + k0+2*t],   W2[(f0+g)*HID + k0+2*t+1],
                     W2[(f0+g)*HID + k0+2*t+8], W2[(f0+g)*HID + k0+2*t+9]);
    if (ks < 4) {   // L0: K=64
        int idx = (nt * 4 + ks) * 32 + lane;
        g_f0[idx] = mkfrag(W0[(k0+2*t)*HID + f0+g],   W0[(k0+2*t+1)*HID + f0+g],
                           W0[(k0+2*t+8)*HID + f0+g], W0[(k0+2*t+9)*HID + f0+g]);
    }
    if (nt < 8) {   // B3: B[j][m] = W0[m][j]; i == (nt*16+ks)*32+lane here
        g_b0[i] = mkfrag(W0[(f0+g)*HID + k0+2*t],   W0[(f0+g)*HID + k0+2*t+1],
                         W0[(f0+g)*HID + k0+2*t+8], W0[(f0+g)*HID + k0+2*t+9]);
    }
}

// ---------------- mma / ldmatrix helpers ----------------
__device__ __forceinline__ uint32_t smem_u32(const void* p) {
    uint32_t a;
    asm("{ .reg .u64 t; cvta.to.shared.u64 t, %1; cvt.u32.u64 %0, t; }" : "=r"(a) : "l"(p));
    return a;
}
__device__ __forceinline__ void ldm4(uint32_t r[4], uint32_t addr) {
    asm volatile("ldmatrix.sync.aligned.m8n8.x4.shared.b16 {%0,%1,%2,%3}, [%4];"
        : "=r"(r[0]), "=r"(r[1]), "=r"(r[2]), "=r"(r[3]) : "r"(addr));
}
__device__ __forceinline__ void mma16(float c[4], const uint32_t a[4],
                                      uint32_t b0, uint32_t b1) {
    asm volatile("mma.sync.aligned.m16n8k16.row.col.f32.bf16.bf16.f32 "
        "{%0,%1,%2,%3}, {%4,%5,%6,%7}, {%8,%9}, {%0,%1,%2,%3};"
        : "+f"(c[0]), "+f"(c[1]), "+f"(c[2]), "+f"(c[3])
        : "r"(a[0]), "r"(a[1]), "r"(a[2]), "r"(a[3]), "r"(b0), "r"(b1));
}

// split-bf16 GEMM: C[32s][256f] = A x B, warp covers (mt, ng*4..ng*4+3) tiles
__device__ __forceinline__ void gemm_layer(float c[4][4],
    uint32_t tH, uint32_t tL, const uint4* __restrict__ wf,
    int ksteps, uint32_t abase, int ng, int lane)
{
    #pragma unroll
    for (int j = 0; j < 4; j++)
        #pragma unroll
        for (int q = 0; q < 4; q++) c[j][q] = 0.f;
    for (int ks = 0; ks < ksteps; ks++) {
        uint32_t ah[4], al[4];
        ldm4(ah, tH + abase + ks * 32);
        ldm4(al, tL + abase + ks * 32);
        #pragma unroll
        for (int j = 0; j < 4; j++) {
            uint4 b = wf[((ng * 4 + j) * ksteps + ks) * 32 + lane];
            mma16(c[j], ah, b.x, b.y);   // Ah * Bh
            mma16(c[j], ah, b.z, b.w);   // Ah * Bl
            mma16(c[j], al, b.x, b.y);   // Al * Bh
        }
    }
}

// store a (f, f+1) value pair as hi/lo bf16 into activation tile
__device__ __forceinline__ void split_st(char* th, char* tl, int s, int fc,
                                         float x, float y) {
    uint32_t off = (uint32_t)s * TROW + (uint32_t)fc * 2;
    *(uint32_t*)(th + off) = pkbf2(x, y);
    *(uint32_t*)(tl + off) = pkbf2(x - bfhi(x), y - bfhi(y));
}

__device__ __forceinline__ void act2(float a, float& sp, float& sg) {
    float e = __expf(-fabsf(a));
    float d = 1.0f + e;
    sp = fmaxf(a, 0.f) + __logf(d);
    sg = (a >= 0.f) ? __fdividef(1.0f, d) : __fdividef(e, d);
}

__global__ __launch_bounds__(NTHR, 1)
void chnn_kernel(const float* __restrict__ z,
                 const float* __restrict__ m_params,
                 const float* __restrict__ b0v, const float* __restrict__ b1v,
                 const float* __restrict__ b2v, const float* __restrict__ W3,
                 float* __restrict__ out)
{
    extern __shared__ char smc[];
    float* zbuf = (float*)(smc + OFF_ZBUF);
    float* invm = (float*)(smc + OFF_INVM);
    float* gbuf = (float*)(smc + OFF_GBUF);
    char* T0h = smc + OFF_T0H; char* T0l = smc + OFF_T0L;
    char* T1h = smc + OFF_T1H; char* T1l = smc + OFF_T1L;

    const int tid = threadIdx.x;
    const int wid = tid >> 5;
    const int lane = tid & 31;
    const int blk = blockIdx.x;
    const int t = lane & 3, g = lane >> 2;
    const int mt = wid & 1;            // m-tile: samples mt*16..mt*16+15
    const int ng = wid >> 1;           // n-group: features ng*32..ng*32+31
    const int s0 = mt * 16 + g;

    const uint32_t smb = smem_u32(smc);
    const uint32_t uT0h = smb + OFF_T0H, uT0l = smb + OFF_T0L;
    const uint32_t uT1h = smb + OFF_T1H, uT1l = smb + OFF_T1L;
    const uint32_t abase = (uint32_t)((lane & 15) + mt * 16) * TROW + ((lane >> 4) << 4);

    // load z tile + invm
    const float* zg = z + (size_t)blk * TB * ZDIM;
    for (int i = tid; i < TB * ZDIM; i += NTHR)
        zbuf[(i >> 7) * ZST + (i & 127)] = zg[i];
    if (tid < NND) invm[tid] = __expf(-m_params[tid]);
    __syncthreads();

    // build r tile (L0 A operand) in T0 hi/lo
    for (int i = tid; i < TB * INF; i += NTHR) {
        int s = i >> 6, f = i & 63;
        float x = zbuf[s * ZST + f];
        uint32_t off = (uint32_t)s * TROW + (uint32_t)f * 2;
        __nv_bfloat16 h = __float2bfloat16(x);
        *(__nv_bfloat16*)(T0h + off) = h;
        *(__nv_bfloat16*)(T0l + off) = __float2bfloat16(x - __bfloat162float(h));
    }
    __syncthreads();

    float c[4][4], sA[4][4], sB[4][4];

    // ================= L0: h0 -> T1, sig0 -> sA =================
    gemm_layer(c, uT0h, uT0l, g_f0, 4, abase, ng, lane);
    #pragma unroll
    for (int j = 0; j < 4; j++) {
        int fc = ng * 32 + j * 8 + 2 * t;
        float2 bb = *(const float2*)(b0v + fc);
        float sp0, sp1, sp2, sp3;
        act2(c[j][0] + bb.x, sp0, sA[j][0]);
        act2(c[j][1] + bb.y, sp1, sA[j][1]);
        act2(c[j][2] + bb.x, sp2, sA[j][2]);
        act2(c[j][3] + bb.y, sp3, sA[j][3]);
        split_st(T1h, T1l, s0,     fc, sp0, sp1);
        split_st(T1h, T1l, s0 + 8, fc, sp2, sp3);
    }
    __syncthreads();

    // ================= L1: h1 -> T0, sig1 -> sB =================
    gemm_layer(c, uT1h, uT1l, g_f1, 16, abase, ng, lane);
    #pragma unroll
    for (int j = 0; j < 4; j++) {
        int fc = ng * 32 + j * 8 + 2 * t;
        float2 bb = *(const float2*)(b1v + fc);
        float sp0, sp1, sp2, sp3;
        act2(c[j][0] + bb.x, sp0, sB[j][0]);
        act2(c[j][1] + bb.y, sp1, sB[j][1]);
        act2(c[j][2] + bb.x, sp2, sB[j][2]);
        act2(c[j][3] + bb.y, sp3, sB[j][3]);
        split_st(T0h, T0l, s0,     fc, sp0, sp1);
        split_st(T0h, T0l, s0 + 8, fc, sp2, sp3);
    }
    __syncthreads();

    // ================= L2: da2 = W3[f]*sigmoid(a2) -> T1 =================
    gemm_layer(c, uT0h, uT0l, g_f2, 16, abase, ng, lane);
    #pragma unroll
    for (int j = 0; j < 4; j++) {
        int fc = ng * 32 + j * 8 + 2 * t;
        float2 bb = *(const float2*)(b2v + fc);
        float2 w3 = *(const float2*)(W3 + fc);
        float v[4];
        #pragma unroll
        for (int q = 0; q < 4; q++) {
            float a = c[j][q] + ((q & 1) ? bb.y : bb.x);
            float e = __expf(-fabsf(a));
            float d = 1.0f + e;
            float sg = (a >= 0.f) ? __fdividef(1.0f, d) : __fdividef(e, d);
            v[q] = ((q & 1) ? w3.y : w3.x) * sg;
        }
        split_st(T1h, T1l, s0,     fc, v[0], v[1]);
        split_st(T1h, T1l, s0 + 8, fc, v[2], v[3]);
    }
    __syncthreads();

    // ================= B1: da1 = (da2 @ W2^T) * sig1 -> T0 =================
    gemm_layer(c, uT1h, uT1l, g_b2, 16, abase, ng, lane);
    #pragma unroll
    for (int j = 0; j < 4; j++) {
        int fc = ng * 32 + j * 8 + 2 * t;
        split_st(T0h, T0l, s0,     fc, c[j][0] * sB[j][0], c[j][1] * sB[j][1]);
        split_st(T0h, T0l, s0 + 8, fc, c[j][2] * sB[j][2], c[j][3] * sB[j][3]);
    }
    __syncthreads();

    // ================= B2: da0 = (da1 @ W1^T) * sig0 -> T1 =================
    gemm_layer(c, uT0h, uT0l, g_b1, 16, abase, ng, lane);
    #pragma unroll
    for (int j = 0; j < 4; j++) {
        int fc = ng * 32 + j * 8 + 2 * t;
        split_st(T1h, T1l, s0,     fc, c[j][0] * sA[j][0], c[j][1] * sA[j][1]);
        split_st(T1h, T1l, s0 + 8, fc, c[j][2] * sA[j][2], c[j][3] * sA[j][3]);
    }
    __syncthreads();

    // ================= B3: g = da0 @ W0^T (32x64) -> gbuf =================
    {
        const int mtb = wid >> 3, ntb = wid & 7;
        const uint32_t ab3 = (uint32_t)((lane & 15) + mtb * 16) * TROW + ((lane >> 4) << 4);
        float cg[4] = {0.f, 0.f, 0.f, 0.f};
        for (int ks = 0; ks < 16; ks++) {
            uint32_t ah[4], al[4];
            ldm4(ah, uT1h + ab3 + ks * 32);
            ldm4(al, uT1l + ab3 + ks * 32);
            uint4 b = g_b0[(ntb * 16 + ks) * 32 + lane];
            mma16(cg, ah, b.x, b.y);
            mma16(cg, ah, b.z, b.w);
            mma16(cg, al, b.x, b.y);
        }
        int fm = ntb * 8 + 2 * t;
        int sb0 = mtb * 16 + g;
        gbuf[sb0 * GST + fm]           = cg[0];
        gbuf[sb0 * GST + fm + 1]       = cg[1];
        gbuf[(sb0 + 8) * GST + fm]     = cg[2];
        gbuf[(sb0 + 8) * GST + fm + 1] = cg[3];
    }
    __syncthreads();

    // ================= constraint solve (1 thread / sample) =================
    float* scr = (float*)(smc + OFF_T0H);   // tiles free now: 16896 floats
    float* Ex  = scr + 0  * NND * TB;
    float* Ey  = scr + 1  * NND * TB;
    float* Edx = scr + 2  * NND * TB;
    float* Edy = scr + 3  * NND * TB;
    float* Vx  = scr + 4  * NND * TB;
    float* Vy  = scr + 5  * NND * TB;
    float* Dd  = scr + 6  * NND * TB;
    float* Du  = scr + 7  * NND * TB;
    float* Dl  = scr + 8  * NND * TB;
    float* So  = scr + 9  * NND * TB;
    float* R0  = scr + 10 * NND * TB;
    float* R1  = scr + 11 * NND * TB;
    float* stage = scr + 12 * NND * TB;     // 4128 floats

    if (tid < TB) {
        const int s = tid;
        const float* zr = zbuf + s * ZST;
        {
            float prx = zr[0], pry = zr[1];
            float im  = invm[0];
            float pvx = zr[64] * im, pvy = zr[65] * im;
            Ex[s]  = 2.f * prx;  Ey[s]  = 2.f * pry;
            Edx[s] = 2.f * pvx;  Edy[s] = 2.f * pvy;
            Vx[s] = pvx; Vy[s] = pvy;
            for (int cc = 1; cc < NND; cc++) {
                float rx = zr[2*cc], ry = zr[2*cc+1];
                float imc = invm[cc];
                float vx = zr[64 + 2*cc] * imc, vy = zr[65 + 2*cc] * imc;
                Ex[cc*TB+s]  = 2.f*(prx - rx);  Ey[cc*TB+s]  = 2.f*(pry - ry);
                Edx[cc*TB+s] = 2.f*(pvx - vx);  Edy[cc*TB+s] = 2.f*(pvy - vy);
                Vx[cc*TB+s] = vx; Vy[cc*TB+s] = vy;
                prx = rx; pry = ry; pvx = vx; pvy = vy;
            }
        }
        {
            float e0x = Ex[s],  e0y = Ey[s];
            float d0x = Edx[s], d0y = Edy[s];
            float v0x = Vx[s],  v0y = Vy[s];
            float im0 = invm[0];
            float e1x = Ex[TB+s],  e1y = Ey[TB+s];
            float d1x = Edx[TB+s], d1y = Edy[TB+s];
            Dd[s] = im0 * (e0x*e0x + e0y*e0y);
            Du[s] = im0 * (e0x*e1x + e0y*e1y);
            So[s] = im0 * (d0x*e1x + d0y*e1y - d1x*e0x - d1y*e0y);
            R0[s] = e0x*v0x + e0y*v0y;
            float g0x = gbuf[s*GST + 0], g0y = gbuf[s*GST + 1];
            R1[s] = d0x*v0x + d0y*v0y - im0*(e0x*g0x + e0y*g0y);
            for (int cc = 1; cc < NND; cc++) {
                float ecx = Ex[cc*TB+s],  ecy = Ey[cc*TB+s];
                float dcx = Edx[cc*TB+s], dcy = Edy[cc*TB+s];
                float imc = invm[cc], imp = invm[cc-1];
                Dd[cc*TB+s] = (imp + imc) * (ecx*ecx + ecy*ecy);
                R0[cc*TB+s] = 0.5f * (ecx*dcx + ecy*dcy);
                float gpx = gbuf[s*GST + 2*(cc-1)], gpy = gbuf[s*GST + 2*(cc-1)+1];
                float gcx = gbuf[s*GST + 2*cc],     gcy = gbuf[s*GST + 2*cc+1];
                R1[cc*TB+s] = 0.5f*(dcx*dcx + dcy*dcy)
                           - (ecx*(imp*gpx - imc*gcx) + ecy*(imp*gpy - imc*gcy));
                if (cc < NND - 1) {
                    float enx = Ex[(cc+1)*TB+s],  eny = Ey[(cc+1)*TB+s];
                    float dnx = Edx[(cc+1)*TB+s], dny = Edy[(cc+1)*TB+s];
                    Du[cc*TB+s] = -imc * (ecx*enx + ecy*eny);
                    So[cc*TB+s] =  imc * (dnx*ecx + dny*ecy - dcx*enx - dcy*eny);
                }
            }
        }
        for (int cc = 1; cc < NND; cc++) {
            float l = Du[(cc-1)*TB+s] / Dd[(cc-1)*TB+s];
            Dl[cc*TB+s] = l;
            Dd[cc*TB+s] = Dd[cc*TB+s] - l * Du[(cc-1)*TB+s];
        }
        for (int cc = 1; cc < NND; cc++)
            R0[cc*TB+s] -= Dl[cc*TB+s] * R0[(cc-1)*TB+s];
        R0[(NND-1)*TB+s] /= Dd[(NND-1)*TB+s];
        for (int cc = NND - 2; cc >= 0; cc--)
            R0[cc*TB+s] = (R0[cc*TB+s] - Du[cc*TB+s] * R0[(cc+1)*TB+s]) / Dd[cc*TB+s];
        R1[s] = So[s] * R0[TB+s] - R1[s];
        for (int cc = 1; cc < NND - 1; cc++)
            R1[cc*TB+s] = So[cc*TB+s]*R0[(cc+1)*TB+s] - So[(cc-1)*TB+s]*R0[(cc-1)*TB+s] - R1[cc*TB+s];
        R1[(NND-1)*TB+s] = -So[(NND-2)*TB+s]*R0[(NND-2)*TB+s] - R1[(NND-1)*TB+s];
        for (int cc = 1; cc < NND; cc++)
            R1[cc*TB+s] -= Dl[cc*TB+s] * R1[(cc-1)*TB+s];
        R1[(NND-1)*TB+s] /= Dd[(NND-1)*TB+s];
        for (int cc = NND - 2; cc >= 0; cc--)
            R1[cc*TB+s] = (R1[cc*TB+s] - Du[cc*TB+s]*R1[(cc+1)*TB+s]) / Dd[cc*TB+s];

        float* st = stage + s * SST;
        for (int i = 0; i < NND; i++) {
            float eix = Ex[i*TB+s],  eiy = Ey[i*TB+s];
            float dix = Edx[i*TB+s], diy = Edy[i*TB+s];
            float x1i = R0[i*TB+s],  x0i = R1[i*TB+s];
            float p1x, p1y, p0x, p0y, pdx, pdy;
            if (i == 0) {
                float enx = Ex[TB+s],  eny = Ey[TB+s];
                float dnx = Edx[TB+s], dny = Edy[TB+s];
                float x1n = R0[TB+s],  x0n = R1[TB+s];
                p1x = eix*x1i + enx*x1n;  p1y = eiy*x1i + eny*x1n;
                p0x = eix*x0i + enx*x0n;  p0y = eiy*x0i + eny*x0n;
                pdx = dix*x1i + dnx*x1n;  pdy = diy*x1i + dny*x1n;
            } else if (i < NND - 1) {
                float enx = Ex[(i+1)*TB+s],  eny = Ey[(i+1)*TB+s];
                float dnx = Edx[(i+1)*TB+s], dny = Edy[(i+1)*TB+s];
                float x1n = R0[(i+1)*TB+s],  x0n = R1[(i+1)*TB+s];
                p1x = -eix*x1i + enx*x1n;  p1y = -eiy*x1i + eny*x1n;
                p0x = -eix*x0i + enx*x0n;  p0y = -eiy*x0i + eny*x0n;
                pdx = -dix*x1i + dnx*x1n;  pdy = -diy*x1i + dny*x1n;
            } else {
                p1x = -eix*x1i; p1y = -eiy*x1i;
                p0x = -eix*x0i; p0y = -eiy*x0i;
                pdx = -dix*x1i; pdy = -diy*x1i;
            }
            float imi = invm[i];
            st[2*i]     = Vx[i*TB+s] - imi * p1x;
            st[2*i + 1] = Vy[i*TB+s] - imi * p1y;
            float gx = gbuf[s*GST + 2*i], gy = gbuf[s*GST + 2*i + 1];
            st[64 + 2*i]     = -gx + p0x + pdx;
            st[64 + 2*i + 1] = -gy + p0y + pdy;
        }
    }
    __syncthreads();

    // coalesced store
    float* outg = out + (size_t)blk * TB * ZDIM;
    for (int i = tid; i < TB * ZDIM; i += NTHR)
        outg[i] = stage[(i >> 7) * SST + (i & 127)];
}

extern "C" void kernel_launch(void* const* d_in, const int* in_sizes, int n_in,
                              void* d_out, int out_size)
{
    (void)in_sizes; (void)n_in; (void)out_size;
    const float* z  = (const float*)d_in[1];
    const float* mp = (const float*)d_in[2];
    const float* W0 = (const float*)d_in[3];
    const float* b0 = (const float*)d_in[4];
    const float* W1 = (const float*)d_in[5];
    const float* b1 = (const float*)d_in[6];
    const float* W2 = (const float*)d_in[7];
    const float* b2 = (const float*)d_in[8];
    const float* W3 = (const float*)d_in[9];
    float* out = (float*)d_out;

    prep_k<<<64, 256>>>(W0, W1, W2);

    cudaFuncSetAttribute(chnn_kernel, cudaFuncAttributeMaxDynamicSharedMemorySize,
                         SMEM_BYTES);
    chnn_kernel<<<NCTA, NTHR, SMEM_BYTES>>>(z, mp, b0, b1, b2, W3, out);
}

// round 8
// speedup vs baseline: 8.5025x; 1.0513x over previous
#include <cuda_runtime.h>
#include <cuda_bf16.h>
#include <stdint.h>
#include <math.h>

#define BSZ   4096
#define NND   32
#define ZDIM  128
#define HID   256
#define INF   64
#define TB    16
#define NTHR  256
#define NCTA  (BSZ / TB)

#define ZST   132
#define GST   65
#define SST   129
#define TROW  528           // bytes per activation-tile row (264 bf16, conflict-free)

// dynamic smem byte offsets (TB=16)
#define OFF_ZBUF  0         // 16*132*4 = 8448 B
#define OFF_INVM  8448      // 32 f = 128 B
#define OFF_GBUF  8576      // 16*65*4 = 4160 B
#define OFF_T0H   12800     // 16*528 = 8448 B each tile
#define OFF_T0L   21248
#define OFF_T1H   29696
#define OFF_T1L   38144
#define SMEM_BYTES 46592

// ---------------- pre-packed weight fragments (B operand of m16n8k16) ----
// layout [ntile][kstep][lane] : uint4 {h0, h1, l0, l1}
__device__ uint4 g_f0[32 * 4 * 32];    // L0 fwd: B[k][f] = W0[k][f], K=64
__device__ uint4 g_f1[32 * 16 * 32];   // L1 fwd: W1[k][f]
__device__ uint4 g_f2[32 * 16 * 32];   // L2 fwd: W2[k][f]
__device__ uint4 g_b2[32 * 16 * 32];   // B1 bwd: B[j][f] = W2[f][j]
__device__ uint4 g_b1[32 * 16 * 32];   // B2 bwd: B[j][f] = W1[f][j]
__device__ uint4 g_b0[8 * 16 * 32];    // B3 bwd: B[j][m] = W0[m][j], N=64

__device__ __forceinline__ uint32_t pkbf2(float lo, float hi) {
    uint32_t r;
    asm("cvt.rn.bf16x2.f32 %0, %1, %2;" : "=r"(r) : "f"(hi), "f"(lo));
    return r;
}
__device__ __forceinline__ float bfhi(float x) {
    return __bfloat162float(__float2bfloat16(x));
}
__device__ __forceinline__ uint4 mkfrag(float a0, float a1, float a2, float a3) {
    uint4 q;
    q.x = pkbf2(a0, a1);
    q.y = pkbf2(a2, a3);
    q.z = pkbf2(a0 - bfhi(a0), a1 - bfhi(a1));
    q.w = pkbf2(a2 - bfhi(a2), a3 - bfhi(a3));
    return q;
}

__global__ void prep_k(const float* __restrict__ W0,
                       const float* __restrict__ W1,
                       const float* __restrict__ W2)
{
    int i = blockIdx.x * blockDim.x + threadIdx.x;    // 0..16383
    if (i >= 16384) return;
    int lane = i & 31, ks = (i >> 5) & 15, nt = i >> 9;
    int t = lane & 3, g = lane >> 2;
    int k0 = ks * 16, f0 = nt * 8;

    g_f1[i] = mkfrag(W1[(k0+2*t)*HID + f0+g],   W1[(k0+2*t+1)*HID + f0+g],
                     W1[(k0+2*t+8)*HID + f0+g], W1[(k0+2*t+9)*HID + f0+g]);
    g_f2[i] = mkfrag(W2[(k0+2*t)*HID + f0+g],   W2[(k0+2*t+1)*HID + f0+g],
                     W2[(k0+2*t+8)*HID + f0+g], W2[(k0+2*t+9)*HID + f0+g]);
    g_b1[i] = mkfrag(W1[(f0+g)*HID + k0+2*t],   W1[(f0+g)*HID + k0+2*t+1],
                     W1[(f0+g)*HID + k0+2*t+8], W1[(f0+g)*HID + k0+2*t+9]);
    g_b2[i] = mkfrag(W2[(f0+g)*HID + k0+2*t],   W2[(f0+g)*HID + k0+2*t+1],
                     W2[(f0+g)*HID + k0+2*t+8], W2[(f0+g)*HID + k0+2*t+9]);
    if (ks < 4) {
        int idx = (nt * 4 + ks) * 32 + lane;
        g_f0[idx] = mkfrag(W0[(k0+2*t)*HID + f0+g],   W0[(k0+2*t+1)*HID + f0+g],
                           W0[(k0+2*t+8)*HID + f0+g], W0[(k0+2*t+9)*HID + f0+g]);
    }
    if (nt < 8) {
        g_b0[i] = mkfrag(W0[(f0+g)*HID + k0+2*t],   W0[(f0+g)*HID + k0+2*t+1],
                         W0[(f0+g)*HID + k0+2*t+8], W0[(f0+g)*HID + k0+2*t+9]);
    }
}

// ---------------- mma / ldmatrix helpers ----------------
__device__ __forceinline__ uint32_t smem_u32(const void* p) {
    uint32_t a;
    asm("{ .reg .u64 t; cvta.to.shared.u64 t, %1; cvt.u32.u64 %0, t; }" : "=r"(a) : "l"(p));
    return a;
}
__device__ __forceinline__ void ldm4(uint32_t r[4], uint32_t addr) {
    asm volatile("ldmatrix.sync.aligned.m8n8.x4.shared.b16 {%0,%1,%2,%3}, [%4];"
        : "=r"(r[0]), "=r"(r[1]), "=r"(r[2]), "=r"(r[3]) : "r"(addr));
}
__device__ __forceinline__ void mma16(float c[4], const uint32_t a[4],
                                      uint32_t b0, uint32_t b1) {
    asm volatile("mma.sync.aligned.m16n8k16.row.col.f32.bf16.bf16.f32 "
        "{%0,%1,%2,%3}, {%4,%5,%6,%7}, {%8,%9}, {%0,%1,%2,%3};"
        : "+f"(c[0]), "+f"(c[1]), "+f"(c[2]), "+f"(c[3])
        : "r"(a[0]), "r"(a[1]), "r"(a[2]), "r"(a[3]), "r"(b0), "r"(b1));
}

// split-bf16 GEMM: C[16s][256f] = A x B, warp covers n-tiles ng*4..ng*4+3
__device__ __forceinline__ void gemm_layer(float c[4][4],
    uint32_t tH, uint32_t tL, const uint4* __restrict__ wf,
    int ksteps, uint32_t abase, int ng, int lane)
{
    #pragma unroll
    for (int j = 0; j < 4; j++)
        #pragma unroll
        for (int q = 0; q < 4; q++) c[j][q] = 0.f;
    for (int ks = 0; ks < ksteps; ks++) {
        uint32_t ah[4], al[4];
        ldm4(ah, tH + abase + ks * 32);
        ldm4(al, tL + abase + ks * 32);
        #pragma unroll
        for (int j = 0; j < 4; j++) {
            uint4 b = wf[((ng * 4 + j) * ksteps + ks) * 32 + lane];
            mma16(c[j], ah, b.x, b.y);   // Ah * Bh
            mma16(c[j], ah, b.z, b.w);   // Ah * Bl
            mma16(c[j], al, b.x, b.y);   // Al * Bh
        }
    }
}

// store a (f, f+1) value pair as hi/lo bf16 into activation tile
__device__ __forceinline__ void split_st(char* th, char* tl, int s, int fc,
                                         float x, float y) {
    uint32_t off = (uint32_t)s * TROW + (uint32_t)fc * 2;
    *(uint32_t*)(th + off) = pkbf2(x, y);
    *(uint32_t*)(tl + off) = pkbf2(x - bfhi(x), y - bfhi(y));
}

__device__ __forceinline__ void act2(float a, float& sp, float& sg) {
    float e = __expf(-fabsf(a));
    float d = 1.0f + e;
    sp = fmaxf(a, 0.f) + __logf(d);
    sg = (a >= 0.f) ? __fdividef(1.0f, d) : __fdividef(e, d);
}

__global__ __launch_bounds__(NTHR, 2)
void chnn_kernel(const float* __restrict__ z,
                 const float* __restrict__ m_params,
                 const float* __restrict__ b0v, const float* __restrict__ b1v,
                 const float* __restrict__ b2v, const float* __restrict__ W3,
                 float* __restrict__ out)
{
    extern __shared__ char smc[];
    float* zbuf = (float*)(smc + OFF_ZBUF);
    float* invm = (float*)(smc + OFF_INVM);
    float* gbuf = (float*)(smc + OFF_GBUF);
    char* T0h = smc + OFF_T0H; char* T0l = smc + OFF_T0L;
    char* T1h = smc + OFF_T1H; char* T1l = smc + OFF_T1L;

    const int tid = threadIdx.x;
    const int wid = tid >> 5;
    const int lane = tid & 31;
    const int blk = blockIdx.x;
    const int t = lane & 3, g = lane >> 2;
    const int ng = wid;                // n-group: features ng*32..ng*32+31
    const int s0 = g;

    const uint32_t smb = smem_u32(smc);
    const uint32_t uT0h = smb + OFF_T0H, uT0l = smb + OFF_T0L;
    const uint32_t uT1h = smb + OFF_T1H, uT1l = smb + OFF_T1L;
    const uint32_t abase = (uint32_t)(lane & 15) * TROW + ((lane >> 4) << 4);

    // load z tile + invm
    const float* zg = z + (size_t)blk * TB * ZDIM;
    for (int i = tid; i < TB * ZDIM; i += NTHR)
        zbuf[(i >> 7) * ZST + (i & 127)] = zg[i];
    if (tid < NND) invm[tid] = __expf(-m_params[tid]);
    __syncthreads();

    // build r tile (L0 A operand) in T0 hi/lo
    for (int i = tid; i < TB * INF; i += NTHR) {
        int s = i >> 6, f = i & 63;
        float x = zbuf[s * ZST + f];
        uint32_t off = (uint32_t)s * TROW + (uint32_t)f * 2;
        __nv_bfloat16 h = __float2bfloat16(x);
        *(__nv_bfloat16*)(T0h + off) = h;
        *(__nv_bfloat16*)(T0l + off) = __float2bfloat16(x - __bfloat162float(h));
    }
    __syncthreads();

    float c[4][4], sA[4][4], sB[4][4];

    // ================= L0: h0 -> T1, sig0 -> sA =================
    gemm_layer(c, uT0h, uT0l, g_f0, 4, abase, ng, lane);
    #pragma unroll
    for (int j = 0; j < 4; j++) {
        int fc = ng * 32 + j * 8 + 2 * t;
        float2 bb = *(const float2*)(b0v + fc);
        float sp0, sp1, sp2, sp3;
        act2(c[j][0] + bb.x, sp0, sA[j][0]);
        act2(c[j][1] + bb.y, sp1, sA[j][1]);
        act2(c[j][2] + bb.x, sp2, sA[j][2]);
        act2(c[j][3] + bb.y, sp3, sA[j][3]);
        split_st(T1h, T1l, s0,     fc, sp0, sp1);
        split_st(T1h, T1l, s0 + 8, fc, sp2, sp3);
    }
    __syncthreads();

    // ================= L1: h1 -> T0, sig1 -> sB =================
    gemm_layer(c, uT1h, uT1l, g_f1, 16, abase, ng, lane);
    #pragma unroll
    for (int j = 0; j < 4; j++) {
        int fc = ng * 32 + j * 8 + 2 * t;
        float2 bb = *(const float2*)(b1v + fc);
        float sp0, sp1, sp2, sp3;
        act2(c[j][0] + bb.x, sp0, sB[j][0]);
        act2(c[j][1] + bb.y, sp1, sB[j][1]);
        act2(c[j][2] + bb.x, sp2, sB[j][2]);
        act2(c[j][3] + bb.y, sp3, sB[j][3]);
        split_st(T0h, T0l, s0,     fc, sp0, sp1);
        split_st(T0h, T0l, s0 + 8, fc, sp2, sp3);
    }
    __syncthreads();

    // ================= L2: da2 = W3[f]*sigmoid(a2) -> T1 =================
    gemm_layer(c, uT0h, uT0l, g_f2, 16, abase, ng, lane);
    #pragma unroll
    for (int j = 0; j < 4; j++) {
        int fc = ng * 32 + j * 8 + 2 * t;
        float2 bb = *(const float2*)(b2v + fc);
        float2 w3 = *(const float2*)(W3 + fc);
        float v[4];
        #pragma unroll
        for (int q = 0; q < 4; q++) {
            float a = c[j][q] + ((q & 1) ? bb.y : bb.x);
            float e = __expf(-fabsf(a));
            float d = 1.0f + e;
            float sg = (a >= 0.f) ? __fdividef(1.0f, d) : __fdividef(e, d);
            v[q] = ((q & 1) ? w3.y : w3.x) * sg;
        }
        split_st(T1h, T1l, s0,     fc, v[0], v[1]);
        split_st(T1h, T1l, s0 + 8, fc, v[2], v[3]);
    }
    __syncthreads();

    // ================= B1: da1 = (da2 @ W2^T) * sig1 -> T0 =================
    gemm_layer(c, uT1h, uT1l, g_b2, 16, abase, ng, lane);
    #pragma unroll
    for (int j = 0; j < 4; j++) {
        int fc = ng * 32 + j * 8 + 2 * t;
        split_st(T0h, T0l, s0,     fc, c[j][0] * sB[j][0], c[j][1] * sB[j][1]);
        split_st(T0h, T0l, s0 + 8, fc, c[j][2] * sB[j][2], c[j][3] * sB[j][3]);
    }
    __syncthreads();

    // ================= B2: da0 = (da1 @ W1^T) * sig0 -> T1 =================
    gemm_layer(c, uT0h, uT0l, g_b1, 16, abase, ng, lane);
    #pragma unroll
    for (int j = 0; j < 4; j++) {
        int fc = ng * 32 + j * 8 + 2 * t;
        split_st(T1h, T1l, s0,     fc, c[j][0] * sA[j][0], c[j][1] * sA[j][1]);
        split_st(T1h, T1l, s0 + 8, fc, c[j][2] * sA[j][2], c[j][3] * sA[j][3]);
    }
    __syncthreads();

    // ================= B3: g = da0 @ W0^T (16x64) -> gbuf =================
    {
        const int ntb = wid;           // 8 warps, 8 n-tiles
        float cg[4] = {0.f, 0.f, 0.f, 0.f};
        for (int ks = 0; ks < 16; ks++) {
            uint32_t ah[4], al[4];
            ldm4(ah, uT1h + abase + ks * 32);
            ldm4(al, uT1l + abase + ks * 32);
            uint4 b = g_b0[(ntb * 16 + ks) * 32 + lane];
            mma16(cg, ah, b.x, b.y);
            mma16(cg, ah, b.z, b.w);
            mma16(cg, al, b.x, b.y);
        }
        int fm = ntb * 8 + 2 * t;
        gbuf[g * GST + fm]           = cg[0];
        gbuf[g * GST + fm + 1]       = cg[1];
        gbuf[(g + 8) * GST + fm]     = cg[2];
        gbuf[(g + 8) * GST + fm + 1] = cg[3];
    }
    __syncthreads();

    // ================= constraint solve (1 thread / sample) =================
    float* scr = (float*)(smc + OFF_T0H);   // 33792 B = 8448 floats free
    float* Ex  = scr + 0  * NND * TB;
    float* Ey  = scr + 1  * NND * TB;
    float* Edx = scr + 2  * NND * TB;
    float* Edy = scr + 3  * NND * TB;
    float* Vx  = scr + 4  * NND * TB;
    float* Vy  = scr + 5  * NND * TB;
    float* Dd  = scr + 6  * NND * TB;
    float* Du  = scr + 7  * NND * TB;
    float* Dl  = scr + 8  * NND * TB;
    float* So  = scr + 9  * NND * TB;
    float* R0  = scr + 10 * NND * TB;
    float* R1  = scr + 11 * NND * TB;
    float* stage = scr + 12 * NND * TB;     // TB*SST = 2064 floats

    if (tid < TB) {
        const int s = tid;
        const float* zr = zbuf + s * ZST;
        {
            float prx = zr[0], pry = zr[1];
            float im  = invm[0];
            float pvx = zr[64] * im, pvy = zr[65] * im;
            Ex[s]  = 2.f * prx;  Ey[s]  = 2.f * pry;
            Edx[s] = 2.f * pvx;  Edy[s] = 2.f * pvy;
            Vx[s] = pvx; Vy[s] = pvy;
            for (int cc = 1; cc < NND; cc++) {
                float rx = zr[2*cc], ry = zr[2*cc+1];
                float imc = invm[cc];
                float vx = zr[64 + 2*cc] * imc, vy = zr[65 + 2*cc] * imc;
                Ex[cc*TB+s]  = 2.f*(prx - rx);  Ey[cc*TB+s]  = 2.f*(pry - ry);
                Edx[cc*TB+s] = 2.f*(pvx - vx);  Edy[cc*TB+s] = 2.f*(pvy - vy);
                Vx[cc*TB+s] = vx; Vy[cc*TB+s] = vy;
                prx = rx; pry = ry; pvx = vx; pvy = vy;
            }
        }
        {
            float e0x = Ex[s],  e0y = Ey[s];
            float d0x = Edx[s], d0y = Edy[s];
            float v0x = Vx[s],  v0y = Vy[s];
            float im0 = invm[0];
            float e1x = Ex[TB+s],  e1y = Ey[TB+s];
            float d1x = Edx[TB+s], d1y = Edy[TB+s];
            Dd[s] = im0 * (e0x*e0x + e0y*e0y);
            Du[s] = im0 * (e0x*e1x + e0y*e1y);
            So[s] = im0 * (d0x*e1x + d0y*e1y - d1x*e0x - d1y*e0y);
            R0[s] = e0x*v0x + e0y*v0y;
            float g0x = gbuf[s*GST + 0], g0y = gbuf[s*GST + 1];
            R1[s] = d0x*v0x + d0y*v0y - im0*(e0x*g0x + e0y*g0y);
            for (int cc = 1; cc < NND; cc++) {
                float ecx = Ex[cc*TB+s],  ecy = Ey[cc*TB+s];
                float dcx = Edx[cc*TB+s], dcy = Edy[cc*TB+s];
                float imc = invm[cc], imp = invm[cc-1];
                Dd[cc*TB+s] = (imp + imc) * (ecx*ecx + ecy*ecy);
                R0[cc*TB+s] = 0.5f * (ecx*dcx + ecy*dcy);
                float gpx = gbuf[s*GST + 2*(cc-1)], gpy = gbuf[s*GST + 2*(cc-1)+1];
                float gcx = gbuf[s*GST + 2*cc],     gcy = gbuf[s*GST + 2*cc+1];
                R1[cc*TB+s] = 0.5f*(dcx*dcx + dcy*dcy)
                           - (ecx*(imp*gpx - imc*gcx) + ecy*(imp*gpy - imc*gcy));
                if (cc < NND - 1) {
                    float enx = Ex[(cc+1)*TB+s],  eny = Ey[(cc+1)*TB+s];
                    float dnx = Edx[(cc+1)*TB+s], dny = Edy[(cc+1)*TB+s];
                    Du[cc*TB+s] = -imc * (ecx*enx + ecy*eny);
                    So[cc*TB+s] =  imc * (dnx*ecx + dny*ecy - dcx*enx - dcy*eny);
                }
            }
        }
        for (int cc = 1; cc < NND; cc++) {
            float l = Du[(cc-1)*TB+s] / Dd[(cc-1)*TB+s];
            Dl[cc*TB+s] = l;
            Dd[cc*TB+s] = Dd[cc*TB+s] - l * Du[(cc-1)*TB+s];
        }
        for (int cc = 1; cc < NND; cc++)
            R0[cc*TB+s] -= Dl[cc*TB+s] * R0[(cc-1)*TB+s];
        R0[(NND-1)*TB+s] /= Dd[(NND-1)*TB+s];
        for (int cc = NND - 2; cc >= 0; cc--)
            R0[cc*TB+s] = (R0[cc*TB+s] - Du[cc*TB+s] * R0[(cc+1)*TB+s]) / Dd[cc*TB+s];
        R1[s] = So[s] * R0[TB+s] - R1[s];
        for (int cc = 1; cc < NND - 1; cc++)
            R1[cc*TB+s] = So[cc*TB+s]*R0[(cc+1)*TB+s] - So[(cc-1)*TB+s]*R0[(cc-1)*TB+s] - R1[cc*TB+s];
        R1[(NND-1)*TB+s] = -So[(NND-2)*TB+s]*R0[(NND-2)*TB+s] - R1[(NND-1)*TB+s];
        for (int cc = 1; cc < NND; cc++)
            R1[cc*TB+s] -= Dl[cc*TB+s] * R1[(cc-1)*TB+s];
        R1[(NND-1)*TB+s] /= Dd[(NND-1)*TB+s];
        for (int cc = NND - 2; cc >= 0; cc--)
            R1[cc*TB+s] = (R1[cc*TB+s] - Du[cc*TB+s]*R1[(cc+1)*TB+s]) / Dd[cc*TB+s];

        float* st = stage + s * SST;
        for (int i = 0; i < NND; i++) {
            float eix = Ex[i*TB+s],  eiy = Ey[i*TB+s];
            float dix = Edx[i*TB+s], diy = Edy[i*TB+s];
            float x1i = R0[i*TB+s],  x0i = R1[i*TB+s];
            float p1x, p1y, p0x, p0y, pdx, pdy;
            if (i == 0) {
                float enx = Ex[TB+s],  eny = Ey[TB+s];
                float dnx = Edx[TB+s], dny = Edy[TB+s];
                float x1n = R0[TB+s],  x0n = R1[TB+s];
                p1x = eix*x1i + enx*x1n;  p1y = eiy*x1i + eny*x1n;
                p0x = eix*x0i + enx*x0n;  p0y = eiy*x0i + eny*x0n;
                pdx = dix*x1i + dnx*x1n;  pdy = diy*x1i + dny*x1n;
            } else if (i < NND - 1) {
                float enx = Ex[(i+1)*TB+s],  eny = Ey[(i+1)*TB+s];
                float dnx = Edx[(i+1)*TB+s], dny = Edy[(i+1)*TB+s];
                float x1n = R0[(i+1)*TB+s],  x0n = R1[(i+1)*TB+s];
                p1x = -eix*x1i + enx*x1n;  p1y = -eiy*x1i + eny*x1n;
                p0x = -eix*x0i + enx*x0n;  p0y = -eiy*x0i + eny*x0n;
                pdx = -dix*x1i + dnx*x1n;  pdy = -diy*x1i + dny*x1n;
            } else {
                p1x = -eix*x1i; p1y = -eiy*x1i;
                p0x = -eix*x0i; p0y = -eiy*x0i;
                pdx = -dix*x1i; pdy = -diy*x1i;
            }
            float imi = invm[i];
            st[2*i]     = Vx[i*TB+s] - imi * p1x;
            st[2*i + 1] = Vy[i*TB+s] - imi * p1y;
            float gx = gbuf[s*GST + 2*i], gy = gbuf[s*GST + 2*i + 1];
            st[64 + 2*i]     = -gx + p0x + pdx;
            st[64 + 2*i + 1] = -gy + p0y + pdy;
        }
    }
    __syncthreads();

    // coalesced store
    float* outg = out + (size_t)blk * TB * ZDIM;
    for (int i = tid; i < TB * ZDIM; i += NTHR)
        outg[i] = stage[(i >> 7) * SST + (i & 127)];
}

extern "C" void kernel_launch(void* const* d_in, const int* in_sizes, int n_in,
                              void* d_out, int out_size)
{
    (void)in_sizes; (void)n_in; (void)out_size;
    const float* z  = (const float*)d_in[1];
    const float* mp = (const float*)d_in[2];
    const float* W0 = (const float*)d_in[3];
    const float* b0 = (const float*)d_in[4];
    const float* W1 = (const float*)d_in[5];
    const float* b1 = (const float*)d_in[6];
    const float* W2 = (const float*)d_in[7];
    const float* b2 = (const float*)d_in[8];
    const float* W3 = (const float*)d_in[9];
    float* out = (float*)d_out;

    prep_k<<<64, 256>>>(W0, W1, W2);

    cudaFuncSetAttribute(chnn_kernel, cudaFuncAttributeMaxDynamicSharedMemorySize,
                         SMEM_BYTES);
    chnn_kernel<<<NCTA, NTHR, SMEM_BYTES>>>(z, mp, b0, b1, b2, W3, out);
}